// round 12
// baseline (speedup 1.0000x reference)
#include <cuda_runtime.h>
#include <cuda_fp16.h>
#include <cstdint>

#define NMAX 100000
#define EMAX 1600000
#define HD   256      // concat hidden dim (2*128)
#define NCLS 40
#define PAD  24       // smem row stride in halves (48B, conflict-free, 16B-aligned)
#define STAGES 3
#define FCPAD 264     // fc W smem row stride in halves
#define AGG_BLOCKS 296   // persistent-warp agg grid (2368 warps)

// ---------------- scratch (static device globals; no allocation) -------------
__device__ __align__(16) int g_deg[NMAX];
__device__ int   g_rowptr[NMAX + 1];
__device__ int   g_cursor[NMAX];
__device__ int   g_esrc[EMAX];
__device__ int   g_bsum[128];
__device__ int   g_boff[128];
__device__ __align__(16) __half g_t1[(size_t)NMAX * 128];  // layer-1 pre-agg
__device__ __align__(16) __half g_t2[(size_t)NMAX * 128];  // layer-2 pre-agg
__device__ __align__(16) __half g_xh[(size_t)NMAX * 128];  // x in fp16
__device__ __align__(16) __half g_h1[(size_t)NMAX * HD];   // fp16 [self|neigh]
__device__ __align__(16) __half g_h2[(size_t)NMAX * HD];
__device__ __align__(16) __half g_wt1[256 * 128];          // layer1 W^T fp16 [n][k]
__device__ __align__(16) __half g_wt2[256 * 256];          // layer2 W^T fp16 [n][k]
__device__ __align__(16) __half g_wtfc[48 * 256];          // fc W^T fp16, zero-padded
__device__ float g_inv1[NMAX];
__device__ float g_inv2[NMAX];

// ---------------- mma / cp.async helpers --------------------------------------
__device__ __forceinline__ void mma_f16(float& c0, float& c1, float& c2, float& c3,
                                        uint32_t a0, uint32_t a1, uint32_t a2, uint32_t a3,
                                        uint32_t b0, uint32_t b1) {
    asm volatile(
        "mma.sync.aligned.m16n8k16.row.col.f32.f16.f16.f32 "
        "{%0,%1,%2,%3}, {%4,%5,%6,%7}, {%8,%9}, {%0,%1,%2,%3};"
        : "+f"(c0), "+f"(c1), "+f"(c2), "+f"(c3)
        : "r"(a0), "r"(a1), "r"(a2), "r"(a3), "r"(b0), "r"(b1));
}

__device__ __forceinline__ void ldsm_x4(uint32_t* r, uint32_t addr) {
    asm volatile("ldmatrix.sync.aligned.m8n8.x4.shared.b16 {%0,%1,%2,%3}, [%4];"
                 : "=r"(r[0]), "=r"(r[1]), "=r"(r[2]), "=r"(r[3]) : "r"(addr));
}

__device__ __forceinline__ void cp_async16(uint32_t dst, const void* src, bool pred) {
    int sz = pred ? 16 : 0;
    asm volatile("cp.async.cg.shared.global [%0], [%1], 16, %2;"
                 :: "r"(dst), "l"(src), "r"(sz));
}
__device__ __forceinline__ void cp_commit() {
    asm volatile("cp.async.commit_group;" ::: "memory");
}
template <int N>
__device__ __forceinline__ void cp_wait() {
    asm volatile("cp.async.wait_group %0;" :: "n"(N) : "memory");
}

// ---------------- CSR build --------------------------------------------------
__global__ void count_kernel(const int* __restrict__ dst, int e) {
    int i = blockIdx.x * blockDim.x + threadIdx.x;
    if (i < e) atomicAdd(&g_deg[dst[i]], 1);
}

__global__ void scan_block_sum(int n) {
    int b = blockIdx.x, t = threadIdx.x, lane = t & 31, w = t >> 5;
    int base = b * 1024 + t * 4;
    int s = 0;
    if (base + 3 < n) {
        int4 v = *reinterpret_cast<const int4*>(g_deg + base);
        s = v.x + v.y + v.z + v.w;
    } else {
#pragma unroll
        for (int j = 0; j < 4; j++) { int i = base + j; if (i < n) s += g_deg[i]; }
    }
#pragma unroll
    for (int off = 16; off; off >>= 1) s += __shfl_xor_sync(0xffffffffu, s, off);
    __shared__ int ws[8];
    if (lane == 0) ws[w] = s;
    __syncthreads();
    if (t == 0) {
        int tot = 0;
#pragma unroll
        for (int j = 0; j < 8; j++) tot += ws[j];
        g_bsum[b] = tot;
    }
}

__global__ void scan_block_offsets(int nb, int n) {
    int t = threadIdx.x, lane = t & 31, w = t >> 5;
    int v = (t < nb) ? g_bsum[t] : 0;
    int val = v;
#pragma unroll
    for (int off = 1; off < 32; off <<= 1) {
        int u = __shfl_up_sync(0xffffffffu, val, off);
        if (lane >= off) val += u;
    }
    __shared__ int ws[4];
    if (lane == 31) ws[w] = val;
    __syncthreads();
    int add = 0;
#pragma unroll
    for (int j = 0; j < 4; j++) if (j < w) add += ws[j];
    int incl = val + add;
    if (t < nb) g_boff[t] = incl - v;
    if (t == nb - 1) g_rowptr[n] = incl;
}

__global__ void scan_write(int n) {
    int b = blockIdx.x, t = threadIdx.x, lane = t & 31, w = t >> 5;
    int base = b * 1024 + t * 4;
    int4 v = make_int4(0, 0, 0, 0);
    if (base + 3 < n) v = *reinterpret_cast<const int4*>(g_deg + base);
    else {
        v.x = (base < n)     ? g_deg[base]     : 0;
        v.y = (base + 1 < n) ? g_deg[base + 1] : 0;
        v.z = (base + 2 < n) ? g_deg[base + 2] : 0;
        v.w = (base + 3 < n) ? g_deg[base + 3] : 0;
    }
    int s = v.x + v.y + v.z + v.w;
    int val = s;
#pragma unroll
    for (int off = 1; off < 32; off <<= 1) {
        int u = __shfl_up_sync(0xffffffffu, val, off);
        if (lane >= off) val += u;
    }
    __shared__ int ws[8];
    if (lane == 31) ws[w] = val;
    __syncthreads();
    int wadd = 0;
#pragma unroll
    for (int j = 0; j < 8; j++) if (j < w) wadd += ws[j];
    int e0 = g_boff[b] + wadd + (val - s);
    int e1 = e0 + v.x, e2 = e1 + v.y, e3 = e2 + v.z;
    if (base < n)     { g_rowptr[base]     = e0; g_cursor[base]     = e0; }
    if (base + 1 < n) { g_rowptr[base + 1] = e1; g_cursor[base + 1] = e1; }
    if (base + 2 < n) { g_rowptr[base + 2] = e2; g_cursor[base + 2] = e2; }
    if (base + 3 < n) { g_rowptr[base + 3] = e3; g_cursor[base + 3] = e3; }
}

__global__ void scatter_kernel(const int* __restrict__ src,
                               const int* __restrict__ dst, int e) {
    int i = blockIdx.x * blockDim.x + threadIdx.x;
    if (i < e) {
        int d = dst[i];
        int pos = atomicAdd(&g_cursor[d], 1);
        g_esrc[pos] = src[i];
    }
}

// ---------------- fp16 conversions -------------------------------------------
__global__ void x_to_half(const float* __restrict__ x, __half* __restrict__ xh, int n4) {
    int i = blockIdx.x * blockDim.x + threadIdx.x;
    if (i < n4) {
        float4 v = reinterpret_cast<const float4*>(x)[i];
        __half2 p0 = __floats2half2_rn(v.x, v.y);
        __half2 p1 = __floats2half2_rn(v.z, v.w);
        uint2 u;
        u.x = *reinterpret_cast<uint32_t*>(&p0);
        u.y = *reinterpret_cast<uint32_t*>(&p1);
        reinterpret_cast<uint2*>(xh)[i] = u;
    }
}

// all weight conversions in one launch
__global__ void w_all_to_half(const float* __restrict__ w1s, const float* __restrict__ w1n,
                              const float* __restrict__ w2s, const float* __restrict__ w2n,
                              const float* __restrict__ wfc,
                              __half* __restrict__ wt1, __half* __restrict__ wt2,
                              __half* __restrict__ wtfc) {
    int idx = blockIdx.x * blockDim.x + threadIdx.x;
    if (idx < 32768) {
        int n = idx >> 7, k = idx & 127;
        float v = (n < 128) ? w1s[(size_t)k * 128 + n] : w1n[(size_t)k * 128 + (n - 128)];
        wt1[idx] = __float2half_rn(v);
    } else if (idx < 98304) {
        int j = idx - 32768;
        int n = j >> 8, k = j & 255;
        float v = (n < 128) ? w2s[(size_t)k * 128 + n] : w2n[(size_t)k * 128 + (n - 128)];
        wt2[j] = __float2half_rn(v);
    } else if (idx < 110592) {
        int j = idx - 98304;
        int n = j >> 8, k = j & 255;
        float v = (n < NCLS) ? wfc[(size_t)k * NCLS + n] : 0.f;
        wtfc[j] = __float2half_rn(v);
    }
}

// ------ mean aggregation: persistent warps, grid-stride over nodes ------------
// Degree imbalance is smoothed by each warp sequentially handling ~n/2368 nodes.
__device__ __forceinline__ void add8(float* a, uint4 u) {
    float2 f;
    f = __half22float2(*reinterpret_cast<__half2*>(&u.x)); a[0] += f.x; a[1] += f.y;
    f = __half22float2(*reinterpret_cast<__half2*>(&u.y)); a[2] += f.x; a[3] += f.y;
    f = __half22float2(*reinterpret_cast<__half2*>(&u.z)); a[4] += f.x; a[5] += f.y;
    f = __half22float2(*reinterpret_cast<__half2*>(&u.w)); a[6] += f.x; a[7] += f.y;
}

__global__ void agg_bias_relu_norm(const __half* __restrict__ t, const float* __restrict__ bias,
                                   __half* __restrict__ h, float* __restrict__ invn, int n) {
    int warp0 = (blockIdx.x * blockDim.x + threadIdx.x) >> 5;
    int nwarps = (gridDim.x * blockDim.x) >> 5;
    int lane = threadIdx.x & 31;
    int hf = lane >> 4, sub = lane & 15;
    const uint4* tb = reinterpret_cast<const uint4*>(t);   // 16 uint4 per 128-ch row

    // preload bias fragment once (reused across all nodes this warp handles)
    float bb[8];
    {
        float4 b0 = reinterpret_cast<const float4*>(bias)[sub * 2];
        float4 b1 = reinterpret_cast<const float4*>(bias)[sub * 2 + 1];
        bb[0] = b0.x; bb[1] = b0.y; bb[2] = b0.z; bb[3] = b0.w;
        bb[4] = b1.x; bb[5] = b1.y; bb[6] = b1.z; bb[7] = b1.w;
    }

    for (int gw = warp0; gw < n; gw += nwarps) {
        int beg = g_rowptr[gw], end = g_rowptr[gw + 1];
        float acc[8] = {0.f, 0.f, 0.f, 0.f, 0.f, 0.f, 0.f, 0.f};
        int e = beg;
        for (; e + 8 <= end; e += 8) {
            int s0 = g_esrc[e + hf];
            int s1 = g_esrc[e + 2 + hf];
            int s2 = g_esrc[e + 4 + hf];
            int s3 = g_esrc[e + 6 + hf];
            uint4 u0 = tb[(size_t)s0 * 16 + sub];
            uint4 u1 = tb[(size_t)s1 * 16 + sub];
            uint4 u2 = tb[(size_t)s2 * 16 + sub];
            uint4 u3 = tb[(size_t)s3 * 16 + sub];
            add8(acc, u0); add8(acc, u1); add8(acc, u2); add8(acc, u3);
        }
        for (; e + 2 <= end; e += 2) {
            int s0 = g_esrc[e + hf];
            uint4 u0 = tb[(size_t)s0 * 16 + sub];
            add8(acc, u0);
        }
        if (e < end && hf == 0) {
            uint4 u0 = tb[(size_t)g_esrc[e] * 16 + sub];
            add8(acc, u0);
        }
#pragma unroll
        for (int j = 0; j < 8; j++) acc[j] += __shfl_xor_sync(0xffffffffu, acc[j], 16);

        int cnt = end - beg;
        float inv = 1.0f / (float)(cnt > 0 ? cnt : 1);
        float ss = 0.f;
        if (hf == 0) {
            float o[8];
#pragma unroll
            for (int j = 0; j < 8; j++) {
                o[j] = fmaxf(acc[j] * inv + bb[j], 0.f);
                ss += o[j] * o[j];
            }
            __half* row = h + (size_t)gw * HD;
            __half2 p0 = __floats2half2_rn(o[0], o[1]);
            __half2 p1 = __floats2half2_rn(o[2], o[3]);
            __half2 p2 = __floats2half2_rn(o[4], o[5]);
            __half2 p3 = __floats2half2_rn(o[6], o[7]);
            uint4 wv;
            wv.x = *reinterpret_cast<uint32_t*>(&p0);
            wv.y = *reinterpret_cast<uint32_t*>(&p1);
            wv.z = *reinterpret_cast<uint32_t*>(&p2);
            wv.w = *reinterpret_cast<uint32_t*>(&p3);
            reinterpret_cast<uint4*>(row + 128)[sub] = wv;      // neigh half
            uint4 sv = reinterpret_cast<const uint4*>(row)[sub]; // self half (from GEMM)
            float2 f;
            f = __half22float2(*reinterpret_cast<__half2*>(&sv.x)); ss += f.x * f.x + f.y * f.y;
            f = __half22float2(*reinterpret_cast<__half2*>(&sv.y)); ss += f.x * f.x + f.y * f.y;
            f = __half22float2(*reinterpret_cast<__half2*>(&sv.z)); ss += f.x * f.x + f.y * f.y;
            f = __half22float2(*reinterpret_cast<__half2*>(&sv.w)); ss += f.x * f.x + f.y * f.y;
        }
#pragma unroll
        for (int off = 16; off; off >>= 1) ss += __shfl_xor_sync(0xffffffffu, ss, off);
        if (lane == 0) invn[gw] = 1.0f / fmaxf(sqrtf(ss), 1e-12f);
    }
}

// ---- fused dual-output fp16 GEMM (3-stage cp.async + ldmatrix + m16n8k16) ----
__global__ void __launch_bounds__(512)
gemm_dual_h(const __half* __restrict__ A, int lda, const float* __restrict__ rowScale,
            const __half* __restrict__ Wt, const float* __restrict__ bias1,
            __half* __restrict__ out1, int ldo1, __half* __restrict__ out2, int ldo2,
            int M, int K) {
    __shared__ __align__(16) __half As[STAGES][128][PAD];
    __shared__ __align__(16) __half Bs[STAGES][256][PAD];

    const int t = threadIdx.x;
    const int warp = t >> 5, lane = t & 31;
    const int wm = warp & 3, wn = warp >> 2;   // 4 x 4 warp grid
    const int grp = lane >> 2, qid = lane & 3;
    const int row0 = blockIdx.x * 128;

    const uint32_t asb = (uint32_t)__cvta_generic_to_shared(&As[0][0][0]);
    const uint32_t bsb = (uint32_t)__cvta_generic_to_shared(&Bs[0][0][0]);

    float acc[2][8][4];
#pragma unroll
    for (int i = 0; i < 2; i++)
#pragma unroll
        for (int j = 0; j < 8; j++)
#pragma unroll
            for (int c = 0; c < 4; c++) acc[i][j][c] = 0.f;

    auto issue = [&](int tile, int st) {
        int k0 = tile * 16;
        if (t < 256) {
            int row = t >> 1, hf = t & 1;
            int gr = row0 + row;
            cp_async16(asb + (uint32_t)(((st * 128 + row) * PAD + hf * 8) * 2),
                       A + (size_t)gr * lda + k0 + hf * 8, gr < M);
        }
        {
            int nrow = t >> 1, hf = t & 1;
            cp_async16(bsb + (uint32_t)(((st * 256 + nrow) * PAD + hf * 8) * 2),
                       Wt + (size_t)nrow * K + k0 + hf * 8, true);
        }
        cp_commit();
    };

    const int nT = K / 16;
    issue(0, 0);
    issue(1, 1);
    cp_wait<1>();
    __syncthreads();

    for (int tile = 0; tile < nT; ++tile) {
        int cur = tile % STAGES;
        uint32_t af[2][4], bq[4][4];
#pragma unroll
        for (int mt = 0; mt < 2; ++mt) {
            int m0 = wm * 32 + mt * 16;
            int arow = m0 + (lane & 15);
            int acol = (lane >> 4) * 8;
            ldsm_x4(af[mt], asb + (uint32_t)(((cur * 128 + arow) * PAD + acol) * 2));
        }
#pragma unroll
        for (int np = 0; np < 4; ++np) {
            int n0 = wn * 64 + np * 16;
            int brow = n0 + ((lane >> 4) << 3) + (lane & 7);
            int bcol = ((lane >> 3) & 1) * 8;
            ldsm_x4(bq[np], bsb + (uint32_t)(((cur * 256 + brow) * PAD + bcol) * 2));
        }
#pragma unroll
        for (int mt = 0; mt < 2; ++mt)
#pragma unroll
            for (int nt = 0; nt < 8; ++nt)
                mma_f16(acc[mt][nt][0], acc[mt][nt][1], acc[mt][nt][2], acc[mt][nt][3],
                        af[mt][0], af[mt][1], af[mt][2], af[mt][3],
                        bq[nt >> 1][(nt & 1) * 2], bq[nt >> 1][(nt & 1) * 2 + 1]);

        if (tile + 2 < nT) {
            issue(tile + 2, (tile + 2) % STAGES);
            cp_wait<1>();
        } else {
            cp_wait<0>();
        }
        __syncthreads();
    }

#pragma unroll
    for (int mt = 0; mt < 2; ++mt) {
        int rbase = row0 + wm * 32 + mt * 16 + grp;
        float sc0 = 1.f, sc1 = 1.f;
        if (rowScale != nullptr) {
            if (rbase < M)     sc0 = rowScale[rbase];
            if (rbase + 8 < M) sc1 = rowScale[rbase + 8];
        }
#pragma unroll
        for (int nt = 0; nt < 8; ++nt) {
            int col = wn * 64 + nt * 8 + qid * 2;
            if (col < 128) {
                float b0 = bias1[col], b1 = bias1[col + 1];
                if (rbase < M) {
                    __half2 hv = __floats2half2_rn(fmaxf(acc[mt][nt][0] * sc0 + b0, 0.f),
                                                   fmaxf(acc[mt][nt][1] * sc0 + b1, 0.f));
                    *reinterpret_cast<__half2*>(out1 + (size_t)rbase * ldo1 + col) = hv;
                }
                if (rbase + 8 < M) {
                    __half2 hv = __floats2half2_rn(fmaxf(acc[mt][nt][2] * sc1 + b0, 0.f),
                                                   fmaxf(acc[mt][nt][3] * sc1 + b1, 0.f));
                    *reinterpret_cast<__half2*>(out1 + (size_t)(rbase + 8) * ldo1 + col) = hv;
                }
            } else {
                int c = col - 128;
                if (rbase < M) {
                    __half2 hv = __floats2half2_rn(acc[mt][nt][0] * sc0, acc[mt][nt][1] * sc0);
                    *reinterpret_cast<__half2*>(out2 + (size_t)rbase * ldo2 + c) = hv;
                }
                if (rbase + 8 < M) {
                    __half2 hv = __floats2half2_rn(acc[mt][nt][2] * sc1, acc[mt][nt][3] * sc1);
                    *reinterpret_cast<__half2*>(out2 + (size_t)(rbase + 8) * ldo2 + c) = hv;
                }
            }
        }
    }
}

// ---- tensor-core FC head: out[M x 40] fp32 = (A .* inv) @ Wfc + bias ---------
__global__ void __launch_bounds__(256)
fc_tc(const __half* __restrict__ A, const float* __restrict__ inv,
      const __half* __restrict__ Wt, const float* __restrict__ bias,
      float* __restrict__ out, int M) {
    __shared__ __align__(16) __half As[STAGES][128][PAD];
    __shared__ __align__(16) __half Bs[48][FCPAD];

    const int t = threadIdx.x;
    const int warp = t >> 5, lane = t & 31;
    const int grp = lane >> 2, qid = lane & 3;
    const int row0 = blockIdx.x * 128;

    const uint32_t asb = (uint32_t)__cvta_generic_to_shared(&As[0][0][0]);
    const uint32_t bsb = (uint32_t)__cvta_generic_to_shared(&Bs[0][0]);

    for (int i = t; i < 1536; i += 256) {
        int r = i >> 5, c = (i & 31) << 3;
        *reinterpret_cast<uint4*>(&Bs[r][c]) =
            *reinterpret_cast<const uint4*>(Wt + (size_t)r * 256 + c);
    }

    float acc[5][4];
#pragma unroll
    for (int j = 0; j < 5; j++)
#pragma unroll
        for (int c = 0; c < 4; c++) acc[j][c] = 0.f;

    auto issueA = [&](int tile, int st) {
        int row = t >> 1, hf = t & 1;
        int gr = row0 + row;
        cp_async16(asb + (uint32_t)(((st * 128 + row) * PAD + hf * 8) * 2),
                   A + (size_t)gr * HD + tile * 16 + hf * 8, gr < M);
        cp_commit();
    };

    issueA(0, 0);
    issueA(1, 1);
    cp_wait<1>();
    __syncthreads();

    const int nT = HD / 16;  // 16
    for (int tile = 0; tile < nT; ++tile) {
        int cur = tile % STAGES;
        uint32_t af[4], bq[3][4];
        {
            int arow = warp * 16 + (lane & 15);
            int acol = (lane >> 4) * 8;
            ldsm_x4(af, asb + (uint32_t)(((cur * 128 + arow) * PAD + acol) * 2));
        }
#pragma unroll
        for (int np = 0; np < 3; ++np) {
            int brow = np * 16 + ((lane >> 4) << 3) + (lane & 7);
            int bcol = tile * 16 + ((lane >> 3) & 1) * 8;
            ldsm_x4(bq[np], bsb + (uint32_t)((brow * FCPAD + bcol) * 2));
        }
#pragma unroll
        for (int nt = 0; nt < 5; ++nt)
            mma_f16(acc[nt][0], acc[nt][1], acc[nt][2], acc[nt][3],
                    af[0], af[1], af[2], af[3],
                    bq[nt >> 1][(nt & 1) * 2], bq[nt >> 1][(nt & 1) * 2 + 1]);

        if (tile + 2 < nT) {
            issueA(tile + 2, (tile + 2) % STAGES);
            cp_wait<1>();
        } else {
            cp_wait<0>();
        }
        __syncthreads();
    }

    int rbase = row0 + warp * 16 + grp;
    float sc0 = (rbase < M) ? inv[rbase] : 0.f;
    float sc1 = (rbase + 8 < M) ? inv[rbase + 8] : 0.f;
#pragma unroll
    for (int nt = 0; nt < 5; ++nt) {
        int col = nt * 8 + qid * 2;
        float b0 = bias[col], b1 = bias[col + 1];
        if (rbase < M) {
            float2 v = make_float2(acc[nt][0] * sc0 + b0, acc[nt][1] * sc0 + b1);
            *reinterpret_cast<float2*>(out + (size_t)rbase * NCLS + col) = v;
        }
        if (rbase + 8 < M) {
            float2 v = make_float2(acc[nt][2] * sc1 + b0, acc[nt][3] * sc1 + b1);
            *reinterpret_cast<float2*>(out + (size_t)(rbase + 8) * NCLS + col) = v;
        }
    }
}

// ---------------- launch ------------------------------------------------------
extern "C" void kernel_launch(void* const* d_in, const int* in_sizes, int n_in,
                              void* d_out, int out_size) {
    const float* x   = (const float*)d_in[0];
    const int*   src = (const int*)d_in[1];
    const int*   dst = (const int*)d_in[2];
    const float* w1s = (const float*)d_in[3];
    const float* b1s = (const float*)d_in[4];
    const float* w1n = (const float*)d_in[5];
    const float* b1n = (const float*)d_in[6];
    const float* w2s = (const float*)d_in[7];
    const float* b2s = (const float*)d_in[8];
    const float* w2n = (const float*)d_in[9];
    const float* b2n = (const float*)d_in[10];
    const float* wfc = (const float*)d_in[11];
    const float* bfc = (const float*)d_in[12];

    int N_ = in_sizes[0] / 128;
    int E_ = in_sizes[1];

    __half *t1, *t2, *xh, *h1, *h2, *wt1, *wt2, *wtfc;
    float *inv1, *inv2;
    int* degp;
    cudaGetSymbolAddress((void**)&t1, g_t1);
    cudaGetSymbolAddress((void**)&t2, g_t2);
    cudaGetSymbolAddress((void**)&xh, g_xh);
    cudaGetSymbolAddress((void**)&h1, g_h1);
    cudaGetSymbolAddress((void**)&h2, g_h2);
    cudaGetSymbolAddress((void**)&wt1, g_wt1);
    cudaGetSymbolAddress((void**)&wt2, g_wt2);
    cudaGetSymbolAddress((void**)&wtfc, g_wtfc);
    cudaGetSymbolAddress((void**)&inv1, g_inv1);
    cudaGetSymbolAddress((void**)&inv2, g_inv2);
    cudaGetSymbolAddress((void**)&degp, g_deg);

    // host-side stream/event objects: created once on the first (uncaptured) call
    static cudaStream_t s1 = nullptr;
    static cudaEvent_t evFork = nullptr, evJoin = nullptr;
    if (s1 == nullptr) {
        cudaStreamCreateWithFlags(&s1, cudaStreamNonBlocking);
        cudaEventCreateWithFlags(&evFork, cudaEventDisableTiming);
        cudaEventCreateWithFlags(&evJoin, cudaEventDisableTiming);
    }

    int eblocks = (E_ + 255) / 256;
    int gblocks = (N_ + 127) / 128;        // gemm row tiles
    int nb = (N_ + 1023) / 1024;           // scan chunks

    // ---- fork: CSR build on side stream (overlaps conversions + GEMM1) ----
    cudaEventRecord(evFork, 0);
    cudaStreamWaitEvent(s1, evFork, 0);
    cudaMemsetAsync(degp, 0, (size_t)N_ * sizeof(int), s1);
    count_kernel<<<eblocks, 256, 0, s1>>>(dst, E_);
    scan_block_sum<<<nb, 256, 0, s1>>>(N_);
    scan_block_offsets<<<1, 128, 0, s1>>>(nb, N_);
    scan_write<<<nb, 256, 0, s1>>>(N_);
    scatter_kernel<<<eblocks, 256, 0, s1>>>(src, dst, E_);
    cudaEventRecord(evJoin, s1);

    // ---- main: conversions + layer-1 GEMM ----
    x_to_half<<<(N_ * 32 + 255) / 256, 256>>>(x, xh, N_ * 32);
    w_all_to_half<<<(110592 + 255) / 256, 256>>>(w1s, w1n, w2s, w2n, wfc, wt1, wt2, wtfc);
    gemm_dual_h<<<gblocks, 512>>>(xh, 128, nullptr, wt1, b1s, h1, HD, t1, 128, N_, 128);

    // ---- join: aggregation needs the CSR ----
    cudaStreamWaitEvent(0, evJoin, 0);
    agg_bias_relu_norm<<<AGG_BLOCKS, 256>>>(t1, b1n, h1, inv1, N_);

    // ---- layer 2 ----
    gemm_dual_h<<<gblocks, 512>>>(h1, HD, inv1, wt2, b2s, h2, HD, t2, 128, N_, 256);
    agg_bias_relu_norm<<<AGG_BLOCKS, 256>>>(t2, b2n, h2, inv2, N_);

    // ---- head (tensor-core) ----
    fc_tc<<<gblocks, 256>>>(h2, inv2, wtfc, bfc, (float*)d_out, N_);
}

// round 13
// speedup vs baseline: 1.3486x; 1.3486x over previous
#include <cuda_runtime.h>
#include <cuda_fp16.h>
#include <cstdint>

#define NMAX 100000
#define EMAX 1600000
#define HD   256      // concat hidden dim (2*128)
#define NCLS 40
#define PAD  24       // smem row stride in halves (48B, conflict-free, 16B-aligned)
#define STAGES 3
#define FCPAD 264     // fc W smem row stride in halves
#define AGG_BLOCKS 1184  // persistent-warp agg grid: 8 CTAs/SM x 148 SMs = 64 warps/SM

// ---------------- scratch (static device globals; no allocation) -------------
__device__ __align__(16) int g_deg[NMAX];
__device__ int   g_rowptr[NMAX + 1];
__device__ int   g_cursor[NMAX];
__device__ int   g_esrc[EMAX];
__device__ int   g_bsum[128];
__device__ int   g_boff[128];
__device__ __align__(16) __half g_t1[(size_t)NMAX * 128];  // layer-1 pre-agg
__device__ __align__(16) __half g_t2[(size_t)NMAX * 128];  // layer-2 pre-agg
__device__ __align__(16) __half g_xh[(size_t)NMAX * 128];  // x in fp16
__device__ __align__(16) __half g_h1[(size_t)NMAX * HD];   // fp16 [self|neigh]
__device__ __align__(16) __half g_h2[(size_t)NMAX * HD];
__device__ __align__(16) __half g_wt1[256 * 128];          // layer1 W^T fp16 [n][k]
__device__ __align__(16) __half g_wt2[256 * 256];          // layer2 W^T fp16 [n][k]
__device__ __align__(16) __half g_wtfc[48 * 256];          // fc W^T fp16, zero-padded
__device__ float g_inv1[NMAX];
__device__ float g_inv2[NMAX];

// ---------------- mma / cp.async helpers --------------------------------------
__device__ __forceinline__ void mma_f16(float& c0, float& c1, float& c2, float& c3,
                                        uint32_t a0, uint32_t a1, uint32_t a2, uint32_t a3,
                                        uint32_t b0, uint32_t b1) {
    asm volatile(
        "mma.sync.aligned.m16n8k16.row.col.f32.f16.f16.f32 "
        "{%0,%1,%2,%3}, {%4,%5,%6,%7}, {%8,%9}, {%0,%1,%2,%3};"
        : "+f"(c0), "+f"(c1), "+f"(c2), "+f"(c3)
        : "r"(a0), "r"(a1), "r"(a2), "r"(a3), "r"(b0), "r"(b1));
}

__device__ __forceinline__ void ldsm_x4(uint32_t* r, uint32_t addr) {
    asm volatile("ldmatrix.sync.aligned.m8n8.x4.shared.b16 {%0,%1,%2,%3}, [%4];"
                 : "=r"(r[0]), "=r"(r[1]), "=r"(r[2]), "=r"(r[3]) : "r"(addr));
}

__device__ __forceinline__ void cp_async16(uint32_t dst, const void* src, bool pred) {
    int sz = pred ? 16 : 0;
    asm volatile("cp.async.cg.shared.global [%0], [%1], 16, %2;"
                 :: "r"(dst), "l"(src), "r"(sz));
}
__device__ __forceinline__ void cp_commit() {
    asm volatile("cp.async.commit_group;" ::: "memory");
}
template <int N>
__device__ __forceinline__ void cp_wait() {
    asm volatile("cp.async.wait_group %0;" :: "n"(N) : "memory");
}

// ---------------- CSR build --------------------------------------------------
__global__ void count_kernel(const int* __restrict__ dst, int e) {
    int i = blockIdx.x * blockDim.x + threadIdx.x;
    if (i < e) atomicAdd(&g_deg[dst[i]], 1);
}

__global__ void scan_block_sum(int n) {
    int b = blockIdx.x, t = threadIdx.x, lane = t & 31, w = t >> 5;
    int base = b * 1024 + t * 4;
    int s = 0;
    if (base + 3 < n) {
        int4 v = *reinterpret_cast<const int4*>(g_deg + base);
        s = v.x + v.y + v.z + v.w;
    } else {
#pragma unroll
        for (int j = 0; j < 4; j++) { int i = base + j; if (i < n) s += g_deg[i]; }
    }
#pragma unroll
    for (int off = 16; off; off >>= 1) s += __shfl_xor_sync(0xffffffffu, s, off);
    __shared__ int ws[8];
    if (lane == 0) ws[w] = s;
    __syncthreads();
    if (t == 0) {
        int tot = 0;
#pragma unroll
        for (int j = 0; j < 8; j++) tot += ws[j];
        g_bsum[b] = tot;
    }
}

__global__ void scan_block_offsets(int nb, int n) {
    int t = threadIdx.x, lane = t & 31, w = t >> 5;
    int v = (t < nb) ? g_bsum[t] : 0;
    int val = v;
#pragma unroll
    for (int off = 1; off < 32; off <<= 1) {
        int u = __shfl_up_sync(0xffffffffu, val, off);
        if (lane >= off) val += u;
    }
    __shared__ int ws[4];
    if (lane == 31) ws[w] = val;
    __syncthreads();
    int add = 0;
#pragma unroll
    for (int j = 0; j < 4; j++) if (j < w) add += ws[j];
    int incl = val + add;
    if (t < nb) g_boff[t] = incl - v;
    if (t == nb - 1) g_rowptr[n] = incl;
}

__global__ void scan_write(int n) {
    int b = blockIdx.x, t = threadIdx.x, lane = t & 31, w = t >> 5;
    int base = b * 1024 + t * 4;
    int4 v = make_int4(0, 0, 0, 0);
    if (base + 3 < n) v = *reinterpret_cast<const int4*>(g_deg + base);
    else {
        v.x = (base < n)     ? g_deg[base]     : 0;
        v.y = (base + 1 < n) ? g_deg[base + 1] : 0;
        v.z = (base + 2 < n) ? g_deg[base + 2] : 0;
        v.w = (base + 3 < n) ? g_deg[base + 3] : 0;
    }
    int s = v.x + v.y + v.z + v.w;
    int val = s;
#pragma unroll
    for (int off = 1; off < 32; off <<= 1) {
        int u = __shfl_up_sync(0xffffffffu, val, off);
        if (lane >= off) val += u;
    }
    __shared__ int ws[8];
    if (lane == 31) ws[w] = val;
    __syncthreads();
    int wadd = 0;
#pragma unroll
    for (int j = 0; j < 8; j++) if (j < w) wadd += ws[j];
    int e0 = g_boff[b] + wadd + (val - s);
    int e1 = e0 + v.x, e2 = e1 + v.y, e3 = e2 + v.z;
    if (base < n)     { g_rowptr[base]     = e0; g_cursor[base]     = e0; }
    if (base + 1 < n) { g_rowptr[base + 1] = e1; g_cursor[base + 1] = e1; }
    if (base + 2 < n) { g_rowptr[base + 2] = e2; g_cursor[base + 2] = e2; }
    if (base + 3 < n) { g_rowptr[base + 3] = e3; g_cursor[base + 3] = e3; }
}

__global__ void scatter_kernel(const int* __restrict__ src,
                               const int* __restrict__ dst, int e) {
    int i = blockIdx.x * blockDim.x + threadIdx.x;
    if (i < e) {
        int d = dst[i];
        int pos = atomicAdd(&g_cursor[d], 1);
        g_esrc[pos] = src[i];
    }
}

// ---------------- fp16 conversions -------------------------------------------
__global__ void x_to_half(const float* __restrict__ x, __half* __restrict__ xh, int n4) {
    int i = blockIdx.x * blockDim.x + threadIdx.x;
    if (i < n4) {
        float4 v = reinterpret_cast<const float4*>(x)[i];
        __half2 p0 = __floats2half2_rn(v.x, v.y);
        __half2 p1 = __floats2half2_rn(v.z, v.w);
        uint2 u;
        u.x = *reinterpret_cast<uint32_t*>(&p0);
        u.y = *reinterpret_cast<uint32_t*>(&p1);
        reinterpret_cast<uint2*>(xh)[i] = u;
    }
}

// all weight conversions in one launch
__global__ void w_all_to_half(const float* __restrict__ w1s, const float* __restrict__ w1n,
                              const float* __restrict__ w2s, const float* __restrict__ w2n,
                              const float* __restrict__ wfc,
                              __half* __restrict__ wt1, __half* __restrict__ wt2,
                              __half* __restrict__ wtfc) {
    int idx = blockIdx.x * blockDim.x + threadIdx.x;
    if (idx < 32768) {
        int n = idx >> 7, k = idx & 127;
        float v = (n < 128) ? w1s[(size_t)k * 128 + n] : w1n[(size_t)k * 128 + (n - 128)];
        wt1[idx] = __float2half_rn(v);
    } else if (idx < 98304) {
        int j = idx - 32768;
        int n = j >> 8, k = j & 255;
        float v = (n < 128) ? w2s[(size_t)k * 128 + n] : w2n[(size_t)k * 128 + (n - 128)];
        wt2[j] = __float2half_rn(v);
    } else if (idx < 110592) {
        int j = idx - 98304;
        int n = j >> 8, k = j & 255;
        float v = (n < NCLS) ? wfc[(size_t)k * NCLS + n] : 0.f;
        wtfc[j] = __float2half_rn(v);
    }
}

// ------ mean aggregation: persistent warps (full occupancy), grid-stride ------
__device__ __forceinline__ void add8(float* a, uint4 u) {
    float2 f;
    f = __half22float2(*reinterpret_cast<__half2*>(&u.x)); a[0] += f.x; a[1] += f.y;
    f = __half22float2(*reinterpret_cast<__half2*>(&u.y)); a[2] += f.x; a[3] += f.y;
    f = __half22float2(*reinterpret_cast<__half2*>(&u.z)); a[4] += f.x; a[5] += f.y;
    f = __half22float2(*reinterpret_cast<__half2*>(&u.w)); a[6] += f.x; a[7] += f.y;
}

__global__ void agg_bias_relu_norm(const __half* __restrict__ t, const float* __restrict__ bias,
                                   __half* __restrict__ h, float* __restrict__ invn, int n) {
    int warp0 = (blockIdx.x * blockDim.x + threadIdx.x) >> 5;
    int nwarps = (gridDim.x * blockDim.x) >> 5;
    int lane = threadIdx.x & 31;
    int hf = lane >> 4, sub = lane & 15;
    const uint4* tb = reinterpret_cast<const uint4*>(t);   // 16 uint4 per 128-ch row

    // preload bias fragment once (reused across all nodes this warp handles)
    float bb[8];
    {
        float4 b0 = reinterpret_cast<const float4*>(bias)[sub * 2];
        float4 b1 = reinterpret_cast<const float4*>(bias)[sub * 2 + 1];
        bb[0] = b0.x; bb[1] = b0.y; bb[2] = b0.z; bb[3] = b0.w;
        bb[4] = b1.x; bb[5] = b1.y; bb[6] = b1.z; bb[7] = b1.w;
    }

    for (int gw = warp0; gw < n; gw += nwarps) {
        int beg = g_rowptr[gw], end = g_rowptr[gw + 1];
        float acc[8] = {0.f, 0.f, 0.f, 0.f, 0.f, 0.f, 0.f, 0.f};
        int e = beg;
        for (; e + 8 <= end; e += 8) {
            int s0 = g_esrc[e + hf];
            int s1 = g_esrc[e + 2 + hf];
            int s2 = g_esrc[e + 4 + hf];
            int s3 = g_esrc[e + 6 + hf];
            uint4 u0 = tb[(size_t)s0 * 16 + sub];
            uint4 u1 = tb[(size_t)s1 * 16 + sub];
            uint4 u2 = tb[(size_t)s2 * 16 + sub];
            uint4 u3 = tb[(size_t)s3 * 16 + sub];
            add8(acc, u0); add8(acc, u1); add8(acc, u2); add8(acc, u3);
        }
        for (; e + 2 <= end; e += 2) {
            int s0 = g_esrc[e + hf];
            uint4 u0 = tb[(size_t)s0 * 16 + sub];
            add8(acc, u0);
        }
        if (e < end && hf == 0) {
            uint4 u0 = tb[(size_t)g_esrc[e] * 16 + sub];
            add8(acc, u0);
        }
#pragma unroll
        for (int j = 0; j < 8; j++) acc[j] += __shfl_xor_sync(0xffffffffu, acc[j], 16);

        int cnt = end - beg;
        float inv = 1.0f / (float)(cnt > 0 ? cnt : 1);
        float ss = 0.f;
        if (hf == 0) {
            float o[8];
#pragma unroll
            for (int j = 0; j < 8; j++) {
                o[j] = fmaxf(acc[j] * inv + bb[j], 0.f);
                ss += o[j] * o[j];
            }
            __half* row = h + (size_t)gw * HD;
            __half2 p0 = __floats2half2_rn(o[0], o[1]);
            __half2 p1 = __floats2half2_rn(o[2], o[3]);
            __half2 p2 = __floats2half2_rn(o[4], o[5]);
            __half2 p3 = __floats2half2_rn(o[6], o[7]);
            uint4 wv;
            wv.x = *reinterpret_cast<uint32_t*>(&p0);
            wv.y = *reinterpret_cast<uint32_t*>(&p1);
            wv.z = *reinterpret_cast<uint32_t*>(&p2);
            wv.w = *reinterpret_cast<uint32_t*>(&p3);
            reinterpret_cast<uint4*>(row + 128)[sub] = wv;      // neigh half
            uint4 sv = reinterpret_cast<const uint4*>(row)[sub]; // self half (from GEMM)
            float2 f;
            f = __half22float2(*reinterpret_cast<__half2*>(&sv.x)); ss += f.x * f.x + f.y * f.y;
            f = __half22float2(*reinterpret_cast<__half2*>(&sv.y)); ss += f.x * f.x + f.y * f.y;
            f = __half22float2(*reinterpret_cast<__half2*>(&sv.z)); ss += f.x * f.x + f.y * f.y;
            f = __half22float2(*reinterpret_cast<__half2*>(&sv.w)); ss += f.x * f.x + f.y * f.y;
        }
#pragma unroll
        for (int off = 16; off; off >>= 1) ss += __shfl_xor_sync(0xffffffffu, ss, off);
        if (lane == 0) invn[gw] = 1.0f / fmaxf(sqrtf(ss), 1e-12f);
    }
}

// ---- fused dual-output fp16 GEMM (3-stage cp.async + ldmatrix + m16n8k16) ----
__global__ void __launch_bounds__(512)
gemm_dual_h(const __half* __restrict__ A, int lda, const float* __restrict__ rowScale,
            const __half* __restrict__ Wt, const float* __restrict__ bias1,
            __half* __restrict__ out1, int ldo1, __half* __restrict__ out2, int ldo2,
            int M, int K) {
    __shared__ __align__(16) __half As[STAGES][128][PAD];
    __shared__ __align__(16) __half Bs[STAGES][256][PAD];

    const int t = threadIdx.x;
    const int warp = t >> 5, lane = t & 31;
    const int wm = warp & 3, wn = warp >> 2;   // 4 x 4 warp grid
    const int grp = lane >> 2, qid = lane & 3;
    const int row0 = blockIdx.x * 128;

    const uint32_t asb = (uint32_t)__cvta_generic_to_shared(&As[0][0][0]);
    const uint32_t bsb = (uint32_t)__cvta_generic_to_shared(&Bs[0][0][0]);

    float acc[2][8][4];
#pragma unroll
    for (int i = 0; i < 2; i++)
#pragma unroll
        for (int j = 0; j < 8; j++)
#pragma unroll
            for (int c = 0; c < 4; c++) acc[i][j][c] = 0.f;

    auto issue = [&](int tile, int st) {
        int k0 = tile * 16;
        if (t < 256) {
            int row = t >> 1, hf = t & 1;
            int gr = row0 + row;
            cp_async16(asb + (uint32_t)(((st * 128 + row) * PAD + hf * 8) * 2),
                       A + (size_t)gr * lda + k0 + hf * 8, gr < M);
        }
        {
            int nrow = t >> 1, hf = t & 1;
            cp_async16(bsb + (uint32_t)(((st * 256 + nrow) * PAD + hf * 8) * 2),
                       Wt + (size_t)nrow * K + k0 + hf * 8, true);
        }
        cp_commit();
    };

    const int nT = K / 16;
    issue(0, 0);
    issue(1, 1);
    cp_wait<1>();
    __syncthreads();

    for (int tile = 0; tile < nT; ++tile) {
        int cur = tile % STAGES;
        uint32_t af[2][4], bq[4][4];
#pragma unroll
        for (int mt = 0; mt < 2; ++mt) {
            int m0 = wm * 32 + mt * 16;
            int arow = m0 + (lane & 15);
            int acol = (lane >> 4) * 8;
            ldsm_x4(af[mt], asb + (uint32_t)(((cur * 128 + arow) * PAD + acol) * 2));
        }
#pragma unroll
        for (int np = 0; np < 4; ++np) {
            int n0 = wn * 64 + np * 16;
            int brow = n0 + ((lane >> 4) << 3) + (lane & 7);
            int bcol = ((lane >> 3) & 1) * 8;
            ldsm_x4(bq[np], bsb + (uint32_t)(((cur * 256 + brow) * PAD + bcol) * 2));
        }
#pragma unroll
        for (int mt = 0; mt < 2; ++mt)
#pragma unroll
            for (int nt = 0; nt < 8; ++nt)
                mma_f16(acc[mt][nt][0], acc[mt][nt][1], acc[mt][nt][2], acc[mt][nt][3],
                        af[mt][0], af[mt][1], af[mt][2], af[mt][3],
                        bq[nt >> 1][(nt & 1) * 2], bq[nt >> 1][(nt & 1) * 2 + 1]);

        if (tile + 2 < nT) {
            issue(tile + 2, (tile + 2) % STAGES);
            cp_wait<1>();
        } else {
            cp_wait<0>();
        }
        __syncthreads();
    }

#pragma unroll
    for (int mt = 0; mt < 2; ++mt) {
        int rbase = row0 + wm * 32 + mt * 16 + grp;
        float sc0 = 1.f, sc1 = 1.f;
        if (rowScale != nullptr) {
            if (rbase < M)     sc0 = rowScale[rbase];
            if (rbase + 8 < M) sc1 = rowScale[rbase + 8];
        }
#pragma unroll
        for (int nt = 0; nt < 8; ++nt) {
            int col = wn * 64 + nt * 8 + qid * 2;
            if (col < 128) {
                float b0 = bias1[col], b1 = bias1[col + 1];
                if (rbase < M) {
                    __half2 hv = __floats2half2_rn(fmaxf(acc[mt][nt][0] * sc0 + b0, 0.f),
                                                   fmaxf(acc[mt][nt][1] * sc0 + b1, 0.f));
                    *reinterpret_cast<__half2*>(out1 + (size_t)rbase * ldo1 + col) = hv;
                }
                if (rbase + 8 < M) {
                    __half2 hv = __floats2half2_rn(fmaxf(acc[mt][nt][2] * sc1 + b0, 0.f),
                                                   fmaxf(acc[mt][nt][3] * sc1 + b1, 0.f));
                    *reinterpret_cast<__half2*>(out1 + (size_t)(rbase + 8) * ldo1 + col) = hv;
                }
            } else {
                int c = col - 128;
                if (rbase < M) {
                    __half2 hv = __floats2half2_rn(acc[mt][nt][0] * sc0, acc[mt][nt][1] * sc0);
                    *reinterpret_cast<__half2*>(out2 + (size_t)rbase * ldo2 + c) = hv;
                }
                if (rbase + 8 < M) {
                    __half2 hv = __floats2half2_rn(acc[mt][nt][2] * sc1, acc[mt][nt][3] * sc1);
                    *reinterpret_cast<__half2*>(out2 + (size_t)(rbase + 8) * ldo2 + c) = hv;
                }
            }
        }
    }
}

// ---- tensor-core FC head: out[M x 40] fp32 = (A .* inv) @ Wfc + bias ---------
__global__ void __launch_bounds__(256)
fc_tc(const __half* __restrict__ A, const float* __restrict__ inv,
      const __half* __restrict__ Wt, const float* __restrict__ bias,
      float* __restrict__ out, int M) {
    __shared__ __align__(16) __half As[STAGES][128][PAD];
    __shared__ __align__(16) __half Bs[48][FCPAD];

    const int t = threadIdx.x;
    const int warp = t >> 5, lane = t & 31;
    const int grp = lane >> 2, qid = lane & 3;
    const int row0 = blockIdx.x * 128;

    const uint32_t asb = (uint32_t)__cvta_generic_to_shared(&As[0][0][0]);
    const uint32_t bsb = (uint32_t)__cvta_generic_to_shared(&Bs[0][0]);

    for (int i = t; i < 1536; i += 256) {
        int r = i >> 5, c = (i & 31) << 3;
        *reinterpret_cast<uint4*>(&Bs[r][c]) =
            *reinterpret_cast<const uint4*>(Wt + (size_t)r * 256 + c);
    }

    float acc[5][4];
#pragma unroll
    for (int j = 0; j < 5; j++)
#pragma unroll
        for (int c = 0; c < 4; c++) acc[j][c] = 0.f;

    auto issueA = [&](int tile, int st) {
        int row = t >> 1, hf = t & 1;
        int gr = row0 + row;
        cp_async16(asb + (uint32_t)(((st * 128 + row) * PAD + hf * 8) * 2),
                   A + (size_t)gr * HD + tile * 16 + hf * 8, gr < M);
        cp_commit();
    };

    issueA(0, 0);
    issueA(1, 1);
    cp_wait<1>();
    __syncthreads();

    const int nT = HD / 16;  // 16
    for (int tile = 0; tile < nT; ++tile) {
        int cur = tile % STAGES;
        uint32_t af[4], bq[3][4];
        {
            int arow = warp * 16 + (lane & 15);
            int acol = (lane >> 4) * 8;
            ldsm_x4(af, asb + (uint32_t)(((cur * 128 + arow) * PAD + acol) * 2));
        }
#pragma unroll
        for (int np = 0; np < 3; ++np) {
            int brow = np * 16 + ((lane >> 4) << 3) + (lane & 7);
            int bcol = tile * 16 + ((lane >> 3) & 1) * 8;
            ldsm_x4(bq[np], bsb + (uint32_t)((brow * FCPAD + bcol) * 2));
        }
#pragma unroll
        for (int nt = 0; nt < 5; ++nt)
            mma_f16(acc[nt][0], acc[nt][1], acc[nt][2], acc[nt][3],
                    af[0], af[1], af[2], af[3],
                    bq[nt >> 1][(nt & 1) * 2], bq[nt >> 1][(nt & 1) * 2 + 1]);

        if (tile + 2 < nT) {
            issueA(tile + 2, (tile + 2) % STAGES);
            cp_wait<1>();
        } else {
            cp_wait<0>();
        }
        __syncthreads();
    }

    int rbase = row0 + warp * 16 + grp;
    float sc0 = (rbase < M) ? inv[rbase] : 0.f;
    float sc1 = (rbase + 8 < M) ? inv[rbase + 8] : 0.f;
#pragma unroll
    for (int nt = 0; nt < 5; ++nt) {
        int col = nt * 8 + qid * 2;
        float b0 = bias[col], b1 = bias[col + 1];
        if (rbase < M) {
            float2 v = make_float2(acc[nt][0] * sc0 + b0, acc[nt][1] * sc0 + b1);
            *reinterpret_cast<float2*>(out + (size_t)rbase * NCLS + col) = v;
        }
        if (rbase + 8 < M) {
            float2 v = make_float2(acc[nt][2] * sc1 + b0, acc[nt][3] * sc1 + b1);
            *reinterpret_cast<float2*>(out + (size_t)(rbase + 8) * NCLS + col) = v;
        }
    }
}

// ---------------- launch ------------------------------------------------------
extern "C" void kernel_launch(void* const* d_in, const int* in_sizes, int n_in,
                              void* d_out, int out_size) {
    const float* x   = (const float*)d_in[0];
    const int*   src = (const int*)d_in[1];
    const int*   dst = (const int*)d_in[2];
    const float* w1s = (const float*)d_in[3];
    const float* b1s = (const float*)d_in[4];
    const float* w1n = (const float*)d_in[5];
    const float* b1n = (const float*)d_in[6];
    const float* w2s = (const float*)d_in[7];
    const float* b2s = (const float*)d_in[8];
    const float* w2n = (const float*)d_in[9];
    const float* b2n = (const float*)d_in[10];
    const float* wfc = (const float*)d_in[11];
    const float* bfc = (const float*)d_in[12];

    int N_ = in_sizes[0] / 128;
    int E_ = in_sizes[1];

    __half *t1, *t2, *xh, *h1, *h2, *wt1, *wt2, *wtfc;
    float *inv1, *inv2;
    int* degp;
    cudaGetSymbolAddress((void**)&t1, g_t1);
    cudaGetSymbolAddress((void**)&t2, g_t2);
    cudaGetSymbolAddress((void**)&xh, g_xh);
    cudaGetSymbolAddress((void**)&h1, g_h1);
    cudaGetSymbolAddress((void**)&h2, g_h2);
    cudaGetSymbolAddress((void**)&wt1, g_wt1);
    cudaGetSymbolAddress((void**)&wt2, g_wt2);
    cudaGetSymbolAddress((void**)&wtfc, g_wtfc);
    cudaGetSymbolAddress((void**)&inv1, g_inv1);
    cudaGetSymbolAddress((void**)&inv2, g_inv2);
    cudaGetSymbolAddress((void**)&degp, g_deg);

    // host-side stream/event objects: created once on the first (uncaptured) call
    static cudaStream_t s1 = nullptr;
    static cudaEvent_t evFork = nullptr, evJoin = nullptr;
    if (s1 == nullptr) {
        cudaStreamCreateWithFlags(&s1, cudaStreamNonBlocking);
        cudaEventCreateWithFlags(&evFork, cudaEventDisableTiming);
        cudaEventCreateWithFlags(&evJoin, cudaEventDisableTiming);
    }

    int eblocks = (E_ + 255) / 256;
    int gblocks = (N_ + 127) / 128;        // gemm row tiles
    int nb = (N_ + 1023) / 1024;           // scan chunks

    // ---- fork: CSR build on side stream (overlaps conversions + GEMM1) ----
    cudaEventRecord(evFork, 0);
    cudaStreamWaitEvent(s1, evFork, 0);
    cudaMemsetAsync(degp, 0, (size_t)N_ * sizeof(int), s1);
    count_kernel<<<eblocks, 256, 0, s1>>>(dst, E_);
    scan_block_sum<<<nb, 256, 0, s1>>>(N_);
    scan_block_offsets<<<1, 128, 0, s1>>>(nb, N_);
    scan_write<<<nb, 256, 0, s1>>>(N_);
    scatter_kernel<<<eblocks, 256, 0, s1>>>(src, dst, E_);
    cudaEventRecord(evJoin, s1);

    // ---- main: conversions + layer-1 GEMM ----
    x_to_half<<<(N_ * 32 + 255) / 256, 256>>>(x, xh, N_ * 32);
    w_all_to_half<<<(110592 + 255) / 256, 256>>>(w1s, w1n, w2s, w2n, wfc, wt1, wt2, wtfc);
    gemm_dual_h<<<gblocks, 512>>>(xh, 128, nullptr, wt1, b1s, h1, HD, t1, 128, N_, 128);

    // ---- join: aggregation needs the CSR ----
    cudaStreamWaitEvent(0, evJoin, 0);
    agg_bias_relu_norm<<<AGG_BLOCKS, 256>>>(t1, b1n, h1, inv1, N_);

    // ---- layer 2 ----
    gemm_dual_h<<<gblocks, 512>>>(h1, HD, inv1, wt2, b2s, h2, HD, t2, 128, N_, 256);
    agg_bias_relu_norm<<<AGG_BLOCKS, 256>>>(t2, b2n, h2, inv2, N_);

    // ---- head (tensor-core) ----
    fc_tc<<<gblocks, 256>>>(h2, inv2, wtfc, bfc, (float*)d_out, N_);
}

// round 14
// speedup vs baseline: 1.4819x; 1.0988x over previous
#include <cuda_runtime.h>
#include <cuda_fp16.h>
#include <cstdint>

#define NMAX 100000
#define EMAX 1600000
#define HD   256      // concat hidden dim (2*128)
#define NCLS 40
#define PAD  24       // smem row stride in halves (48B, conflict-free, 16B-aligned)
#define STAGES 3
#define FCPAD 264     // fc W smem row stride in halves

// ---------------- scratch (static device globals; no allocation) -------------
__device__ __align__(16) int g_deg[NMAX];
__device__ int   g_rowptr[NMAX + 1];
__device__ int   g_cursor[NMAX];
__device__ int   g_esrc[EMAX];
__device__ int   g_bsum[128];
__device__ int   g_boff[128];
__device__ __align__(16) __half g_t1[(size_t)NMAX * 128];  // layer-1 pre-agg
__device__ __align__(16) __half g_t2[(size_t)NMAX * 128];  // layer-2 pre-agg
__device__ __align__(16) __half g_xh[(size_t)NMAX * 128];  // x in fp16
__device__ __align__(16) __half g_h1[(size_t)NMAX * HD];   // fp16 [self|neigh]
__device__ __align__(16) __half g_h2[(size_t)NMAX * HD];
__device__ __align__(16) __half g_wt1[256 * 128];          // layer1 W^T fp16 [n][k]
__device__ __align__(16) __half g_wt2[256 * 256];          // layer2 W^T fp16 [n][k]
__device__ __align__(16) __half g_wtfc[48 * 256];          // fc W^T fp16, zero-padded
__device__ float g_inv1[NMAX];
__device__ float g_inv2[NMAX];

// ---------------- mma / cp.async helpers --------------------------------------
__device__ __forceinline__ void mma_f16(float& c0, float& c1, float& c2, float& c3,
                                        uint32_t a0, uint32_t a1, uint32_t a2, uint32_t a3,
                                        uint32_t b0, uint32_t b1) {
    asm volatile(
        "mma.sync.aligned.m16n8k16.row.col.f32.f16.f16.f32 "
        "{%0,%1,%2,%3}, {%4,%5,%6,%7}, {%8,%9}, {%0,%1,%2,%3};"
        : "+f"(c0), "+f"(c1), "+f"(c2), "+f"(c3)
        : "r"(a0), "r"(a1), "r"(a2), "r"(a3), "r"(b0), "r"(b1));
}

__device__ __forceinline__ void ldsm_x4(uint32_t* r, uint32_t addr) {
    asm volatile("ldmatrix.sync.aligned.m8n8.x4.shared.b16 {%0,%1,%2,%3}, [%4];"
                 : "=r"(r[0]), "=r"(r[1]), "=r"(r[2]), "=r"(r[3]) : "r"(addr));
}

__device__ __forceinline__ void cp_async16(uint32_t dst, const void* src, bool pred) {
    int sz = pred ? 16 : 0;
    asm volatile("cp.async.cg.shared.global [%0], [%1], 16, %2;"
                 :: "r"(dst), "l"(src), "r"(sz));
}
__device__ __forceinline__ void cp_commit() {
    asm volatile("cp.async.commit_group;" ::: "memory");
}
template <int N>
__device__ __forceinline__ void cp_wait() {
    asm volatile("cp.async.wait_group %0;" :: "n"(N) : "memory");
}

// ---------------- CSR build --------------------------------------------------
__global__ void count_kernel(const int* __restrict__ dst, int e) {
    int i = blockIdx.x * blockDim.x + threadIdx.x;
    if (i < e) atomicAdd(&g_deg[dst[i]], 1);
}

__global__ void scan_block_sum(int n) {
    int b = blockIdx.x, t = threadIdx.x, lane = t & 31, w = t >> 5;
    int base = b * 1024 + t * 4;
    int s = 0;
    if (base + 3 < n) {
        int4 v = *reinterpret_cast<const int4*>(g_deg + base);
        s = v.x + v.y + v.z + v.w;
    } else {
#pragma unroll
        for (int j = 0; j < 4; j++) { int i = base + j; if (i < n) s += g_deg[i]; }
    }
#pragma unroll
    for (int off = 16; off; off >>= 1) s += __shfl_xor_sync(0xffffffffu, s, off);
    __shared__ int ws[8];
    if (lane == 0) ws[w] = s;
    __syncthreads();
    if (t == 0) {
        int tot = 0;
#pragma unroll
        for (int j = 0; j < 8; j++) tot += ws[j];
        g_bsum[b] = tot;
    }
}

__global__ void scan_block_offsets(int nb, int n) {
    int t = threadIdx.x, lane = t & 31, w = t >> 5;
    int v = (t < nb) ? g_bsum[t] : 0;
    int val = v;
#pragma unroll
    for (int off = 1; off < 32; off <<= 1) {
        int u = __shfl_up_sync(0xffffffffu, val, off);
        if (lane >= off) val += u;
    }
    __shared__ int ws[4];
    if (lane == 31) ws[w] = val;
    __syncthreads();
    int add = 0;
#pragma unroll
    for (int j = 0; j < 4; j++) if (j < w) add += ws[j];
    int incl = val + add;
    if (t < nb) g_boff[t] = incl - v;
    if (t == nb - 1) g_rowptr[n] = incl;
}

__global__ void scan_write(int n) {
    int b = blockIdx.x, t = threadIdx.x, lane = t & 31, w = t >> 5;
    int base = b * 1024 + t * 4;
    int4 v = make_int4(0, 0, 0, 0);
    if (base + 3 < n) v = *reinterpret_cast<const int4*>(g_deg + base);
    else {
        v.x = (base < n)     ? g_deg[base]     : 0;
        v.y = (base + 1 < n) ? g_deg[base + 1] : 0;
        v.z = (base + 2 < n) ? g_deg[base + 2] : 0;
        v.w = (base + 3 < n) ? g_deg[base + 3] : 0;
    }
    int s = v.x + v.y + v.z + v.w;
    int val = s;
#pragma unroll
    for (int off = 1; off < 32; off <<= 1) {
        int u = __shfl_up_sync(0xffffffffu, val, off);
        if (lane >= off) val += u;
    }
    __shared__ int ws[8];
    if (lane == 31) ws[w] = val;
    __syncthreads();
    int wadd = 0;
#pragma unroll
    for (int j = 0; j < 8; j++) if (j < w) wadd += ws[j];
    int e0 = g_boff[b] + wadd + (val - s);
    int e1 = e0 + v.x, e2 = e1 + v.y, e3 = e2 + v.z;
    if (base < n)     { g_rowptr[base]     = e0; g_cursor[base]     = e0; }
    if (base + 1 < n) { g_rowptr[base + 1] = e1; g_cursor[base + 1] = e1; }
    if (base + 2 < n) { g_rowptr[base + 2] = e2; g_cursor[base + 2] = e2; }
    if (base + 3 < n) { g_rowptr[base + 3] = e3; g_cursor[base + 3] = e3; }
}

__global__ void scatter_kernel(const int* __restrict__ src,
                               const int* __restrict__ dst, int e) {
    int i = blockIdx.x * blockDim.x + threadIdx.x;
    if (i < e) {
        int d = dst[i];
        int pos = atomicAdd(&g_cursor[d], 1);
        g_esrc[pos] = src[i];
    }
}

// ---------------- fp16 conversions -------------------------------------------
__global__ void x_to_half(const float* __restrict__ x, __half* __restrict__ xh, int n4) {
    int i = blockIdx.x * blockDim.x + threadIdx.x;
    if (i < n4) {
        float4 v = reinterpret_cast<const float4*>(x)[i];
        __half2 p0 = __floats2half2_rn(v.x, v.y);
        __half2 p1 = __floats2half2_rn(v.z, v.w);
        uint2 u;
        u.x = *reinterpret_cast<uint32_t*>(&p0);
        u.y = *reinterpret_cast<uint32_t*>(&p1);
        reinterpret_cast<uint2*>(xh)[i] = u;
    }
}

// all weight conversions in one launch
__global__ void w_all_to_half(const float* __restrict__ w1s, const float* __restrict__ w1n,
                              const float* __restrict__ w2s, const float* __restrict__ w2n,
                              const float* __restrict__ wfc,
                              __half* __restrict__ wt1, __half* __restrict__ wt2,
                              __half* __restrict__ wtfc) {
    int idx = blockIdx.x * blockDim.x + threadIdx.x;
    if (idx < 32768) {
        int n = idx >> 7, k = idx & 127;
        float v = (n < 128) ? w1s[(size_t)k * 128 + n] : w1n[(size_t)k * 128 + (n - 128)];
        wt1[idx] = __float2half_rn(v);
    } else if (idx < 98304) {
        int j = idx - 32768;
        int n = j >> 8, k = j & 255;
        float v = (n < 128) ? w2s[(size_t)k * 128 + n] : w2n[(size_t)k * 128 + (n - 128)];
        wt2[j] = __float2half_rn(v);
    } else if (idx < 110592) {
        int j = idx - 98304;
        int n = j >> 8, k = j & 255;
        float v = (n < NCLS) ? wfc[(size_t)k * NCLS + n] : 0.f;
        wtfc[j] = __float2half_rn(v);
    }
}

// ------ mean aggregation: warp-per-node, uint4/lane, 8 edges/iter (R10 form) --
__device__ __forceinline__ void add8(float* a, uint4 u) {
    float2 f;
    f = __half22float2(*reinterpret_cast<__half2*>(&u.x)); a[0] += f.x; a[1] += f.y;
    f = __half22float2(*reinterpret_cast<__half2*>(&u.y)); a[2] += f.x; a[3] += f.y;
    f = __half22float2(*reinterpret_cast<__half2*>(&u.z)); a[4] += f.x; a[5] += f.y;
    f = __half22float2(*reinterpret_cast<__half2*>(&u.w)); a[6] += f.x; a[7] += f.y;
}

__global__ void agg_bias_relu_norm(const __half* __restrict__ t, const float* __restrict__ bias,
                                   __half* __restrict__ h, float* __restrict__ invn,
                                   int nodeOff, int nodeCnt) {
    int w = (blockIdx.x * blockDim.x + threadIdx.x) >> 5;
    if (w >= nodeCnt) return;
    int gw = nodeOff + w;
    int lane = threadIdx.x & 31;
    int hf = lane >> 4, sub = lane & 15;
    int beg = g_rowptr[gw], end = g_rowptr[gw + 1];
    const uint4* tb = reinterpret_cast<const uint4*>(t);   // 16 uint4 per 128-ch row
    float acc[8] = {0.f, 0.f, 0.f, 0.f, 0.f, 0.f, 0.f, 0.f};
    int e = beg;
    for (; e + 8 <= end; e += 8) {
        int s0 = g_esrc[e + hf];
        int s1 = g_esrc[e + 2 + hf];
        int s2 = g_esrc[e + 4 + hf];
        int s3 = g_esrc[e + 6 + hf];
        uint4 u0 = tb[(size_t)s0 * 16 + sub];
        uint4 u1 = tb[(size_t)s1 * 16 + sub];
        uint4 u2 = tb[(size_t)s2 * 16 + sub];
        uint4 u3 = tb[(size_t)s3 * 16 + sub];
        add8(acc, u0); add8(acc, u1); add8(acc, u2); add8(acc, u3);
    }
    for (; e + 2 <= end; e += 2) {
        int s0 = g_esrc[e + hf];
        uint4 u0 = tb[(size_t)s0 * 16 + sub];
        add8(acc, u0);
    }
    if (e < end && hf == 0) {
        uint4 u0 = tb[(size_t)g_esrc[e] * 16 + sub];
        add8(acc, u0);
    }
#pragma unroll
    for (int j = 0; j < 8; j++) acc[j] += __shfl_xor_sync(0xffffffffu, acc[j], 16);

    int cnt = end - beg;
    float inv = 1.0f / (float)(cnt > 0 ? cnt : 1);
    float ss = 0.f;
    if (hf == 0) {
        float4 b0 = reinterpret_cast<const float4*>(bias)[sub * 2];
        float4 b1 = reinterpret_cast<const float4*>(bias)[sub * 2 + 1];
        float bb[8] = {b0.x, b0.y, b0.z, b0.w, b1.x, b1.y, b1.z, b1.w};
        float o[8];
#pragma unroll
        for (int j = 0; j < 8; j++) {
            o[j] = fmaxf(acc[j] * inv + bb[j], 0.f);
            ss += o[j] * o[j];
        }
        __half* row = h + (size_t)gw * HD;
        __half2 p0 = __floats2half2_rn(o[0], o[1]);
        __half2 p1 = __floats2half2_rn(o[2], o[3]);
        __half2 p2 = __floats2half2_rn(o[4], o[5]);
        __half2 p3 = __floats2half2_rn(o[6], o[7]);
        uint4 wv;
        wv.x = *reinterpret_cast<uint32_t*>(&p0);
        wv.y = *reinterpret_cast<uint32_t*>(&p1);
        wv.z = *reinterpret_cast<uint32_t*>(&p2);
        wv.w = *reinterpret_cast<uint32_t*>(&p3);
        reinterpret_cast<uint4*>(row + 128)[sub] = wv;      // neigh half
        uint4 sv = reinterpret_cast<const uint4*>(row)[sub]; // self half (from GEMM)
        float2 f;
        f = __half22float2(*reinterpret_cast<__half2*>(&sv.x)); ss += f.x * f.x + f.y * f.y;
        f = __half22float2(*reinterpret_cast<__half2*>(&sv.y)); ss += f.x * f.x + f.y * f.y;
        f = __half22float2(*reinterpret_cast<__half2*>(&sv.z)); ss += f.x * f.x + f.y * f.y;
        f = __half22float2(*reinterpret_cast<__half2*>(&sv.w)); ss += f.x * f.x + f.y * f.y;
    }
#pragma unroll
    for (int off = 16; off; off >>= 1) ss += __shfl_xor_sync(0xffffffffu, ss, off);
    if (lane == 0) invn[gw] = 1.0f / fmaxf(sqrtf(ss), 1e-12f);
}

// ---- fused dual-output fp16 GEMM (3-stage cp.async + ldmatrix + m16n8k16) ----
__global__ void __launch_bounds__(512)
gemm_dual_h(const __half* __restrict__ A, int lda, const float* __restrict__ rowScale,
            const __half* __restrict__ Wt, const float* __restrict__ bias1,
            __half* __restrict__ out1, int ldo1, __half* __restrict__ out2, int ldo2,
            int M, int K) {
    __shared__ __align__(16) __half As[STAGES][128][PAD];
    __shared__ __align__(16) __half Bs[STAGES][256][PAD];

    const int t = threadIdx.x;
    const int warp = t >> 5, lane = t & 31;
    const int wm = warp & 3, wn = warp >> 2;   // 4 x 4 warp grid
    const int grp = lane >> 2, qid = lane & 3;
    const int row0 = blockIdx.x * 128;

    const uint32_t asb = (uint32_t)__cvta_generic_to_shared(&As[0][0][0]);
    const uint32_t bsb = (uint32_t)__cvta_generic_to_shared(&Bs[0][0][0]);

    float acc[2][8][4];
#pragma unroll
    for (int i = 0; i < 2; i++)
#pragma unroll
        for (int j = 0; j < 8; j++)
#pragma unroll
            for (int c = 0; c < 4; c++) acc[i][j][c] = 0.f;

    auto issue = [&](int tile, int st) {
        int k0 = tile * 16;
        if (t < 256) {
            int row = t >> 1, hf = t & 1;
            int gr = row0 + row;
            cp_async16(asb + (uint32_t)(((st * 128 + row) * PAD + hf * 8) * 2),
                       A + (size_t)gr * lda + k0 + hf * 8, gr < M);
        }
        {
            int nrow = t >> 1, hf = t & 1;
            cp_async16(bsb + (uint32_t)(((st * 256 + nrow) * PAD + hf * 8) * 2),
                       Wt + (size_t)nrow * K + k0 + hf * 8, true);
        }
        cp_commit();
    };

    const int nT = K / 16;
    issue(0, 0);
    issue(1, 1);
    cp_wait<1>();
    __syncthreads();

    for (int tile = 0; tile < nT; ++tile) {
        int cur = tile % STAGES;
        uint32_t af[2][4], bq[4][4];
#pragma unroll
        for (int mt = 0; mt < 2; ++mt) {
            int m0 = wm * 32 + mt * 16;
            int arow = m0 + (lane & 15);
            int acol = (lane >> 4) * 8;
            ldsm_x4(af[mt], asb + (uint32_t)(((cur * 128 + arow) * PAD + acol) * 2));
        }
#pragma unroll
        for (int np = 0; np < 4; ++np) {
            int n0 = wn * 64 + np * 16;
            int brow = n0 + ((lane >> 4) << 3) + (lane & 7);
            int bcol = ((lane >> 3) & 1) * 8;
            ldsm_x4(bq[np], bsb + (uint32_t)(((cur * 256 + brow) * PAD + bcol) * 2));
        }
#pragma unroll
        for (int mt = 0; mt < 2; ++mt)
#pragma unroll
            for (int nt = 0; nt < 8; ++nt)
                mma_f16(acc[mt][nt][0], acc[mt][nt][1], acc[mt][nt][2], acc[mt][nt][3],
                        af[mt][0], af[mt][1], af[mt][2], af[mt][3],
                        bq[nt >> 1][(nt & 1) * 2], bq[nt >> 1][(nt & 1) * 2 + 1]);

        if (tile + 2 < nT) {
            issue(tile + 2, (tile + 2) % STAGES);
            cp_wait<1>();
        } else {
            cp_wait<0>();
        }
        __syncthreads();
    }

#pragma unroll
    for (int mt = 0; mt < 2; ++mt) {
        int rbase = row0 + wm * 32 + mt * 16 + grp;
        float sc0 = 1.f, sc1 = 1.f;
        if (rowScale != nullptr) {
            if (rbase < M)     sc0 = rowScale[rbase];
            if (rbase + 8 < M) sc1 = rowScale[rbase + 8];
        }
#pragma unroll
        for (int nt = 0; nt < 8; ++nt) {
            int col = wn * 64 + nt * 8 + qid * 2;
            if (col < 128) {
                float b0 = bias1[col], b1 = bias1[col + 1];
                if (rbase < M) {
                    __half2 hv = __floats2half2_rn(fmaxf(acc[mt][nt][0] * sc0 + b0, 0.f),
                                                   fmaxf(acc[mt][nt][1] * sc0 + b1, 0.f));
                    *reinterpret_cast<__half2*>(out1 + (size_t)rbase * ldo1 + col) = hv;
                }
                if (rbase + 8 < M) {
                    __half2 hv = __floats2half2_rn(fmaxf(acc[mt][nt][2] * sc1 + b0, 0.f),
                                                   fmaxf(acc[mt][nt][3] * sc1 + b1, 0.f));
                    *reinterpret_cast<__half2*>(out1 + (size_t)(rbase + 8) * ldo1 + col) = hv;
                }
            } else {
                int c = col - 128;
                if (rbase < M) {
                    __half2 hv = __floats2half2_rn(acc[mt][nt][0] * sc0, acc[mt][nt][1] * sc0);
                    *reinterpret_cast<__half2*>(out2 + (size_t)rbase * ldo2 + c) = hv;
                }
                if (rbase + 8 < M) {
                    __half2 hv = __floats2half2_rn(acc[mt][nt][2] * sc1, acc[mt][nt][3] * sc1);
                    *reinterpret_cast<__half2*>(out2 + (size_t)(rbase + 8) * ldo2 + c) = hv;
                }
            }
        }
    }
}

// ---- tensor-core FC head: out[M x 40] fp32 = (A .* inv) @ Wfc + bias ---------
__global__ void __launch_bounds__(256)
fc_tc(const __half* __restrict__ A, const float* __restrict__ inv,
      const __half* __restrict__ Wt, const float* __restrict__ bias,
      float* __restrict__ out, int rowOff, int M) {
    __shared__ __align__(16) __half As[STAGES][128][PAD];
    __shared__ __align__(16) __half Bs[48][FCPAD];

    const int t = threadIdx.x;
    const int warp = t >> 5, lane = t & 31;
    const int grp = lane >> 2, qid = lane & 3;
    const int row0 = rowOff + blockIdx.x * 128;

    const uint32_t asb = (uint32_t)__cvta_generic_to_shared(&As[0][0][0]);
    const uint32_t bsb = (uint32_t)__cvta_generic_to_shared(&Bs[0][0]);

    for (int i = t; i < 1536; i += 256) {
        int r = i >> 5, c = (i & 31) << 3;
        *reinterpret_cast<uint4*>(&Bs[r][c]) =
            *reinterpret_cast<const uint4*>(Wt + (size_t)r * 256 + c);
    }

    float acc[5][4];
#pragma unroll
    for (int j = 0; j < 5; j++)
#pragma unroll
        for (int c = 0; c < 4; c++) acc[j][c] = 0.f;

    auto issueA = [&](int tile, int st) {
        int row = t >> 1, hf = t & 1;
        int gr = row0 + row;
        cp_async16(asb + (uint32_t)(((st * 128 + row) * PAD + hf * 8) * 2),
                   A + (size_t)gr * HD + tile * 16 + hf * 8, gr < M);
        cp_commit();
    };

    issueA(0, 0);
    issueA(1, 1);
    cp_wait<1>();
    __syncthreads();

    const int nT = HD / 16;  // 16
    for (int tile = 0; tile < nT; ++tile) {
        int cur = tile % STAGES;
        uint32_t af[4], bq[3][4];
        {
            int arow = warp * 16 + (lane & 15);
            int acol = (lane >> 4) * 8;
            ldsm_x4(af, asb + (uint32_t)(((cur * 128 + arow) * PAD + acol) * 2));
        }
#pragma unroll
        for (int np = 0; np < 3; ++np) {
            int brow = np * 16 + ((lane >> 4) << 3) + (lane & 7);
            int bcol = tile * 16 + ((lane >> 3) & 1) * 8;
            ldsm_x4(bq[np], bsb + (uint32_t)((brow * FCPAD + bcol) * 2));
        }
#pragma unroll
        for (int nt = 0; nt < 5; ++nt)
            mma_f16(acc[nt][0], acc[nt][1], acc[nt][2], acc[nt][3],
                    af[0], af[1], af[2], af[3],
                    bq[nt >> 1][(nt & 1) * 2], bq[nt >> 1][(nt & 1) * 2 + 1]);

        if (tile + 2 < nT) {
            issueA(tile + 2, (tile + 2) % STAGES);
            cp_wait<1>();
        } else {
            cp_wait<0>();
        }
        __syncthreads();
    }

    int rbase = row0 + warp * 16 + grp;
    float sc0 = (rbase < M) ? inv[rbase] : 0.f;
    float sc1 = (rbase + 8 < M) ? inv[rbase + 8] : 0.f;
#pragma unroll
    for (int nt = 0; nt < 5; ++nt) {
        int col = nt * 8 + qid * 2;
        float b0 = bias[col], b1 = bias[col + 1];
        if (rbase < M) {
            float2 v = make_float2(acc[nt][0] * sc0 + b0, acc[nt][1] * sc0 + b1);
            *reinterpret_cast<float2*>(out + (size_t)rbase * NCLS + col) = v;
        }
        if (rbase + 8 < M) {
            float2 v = make_float2(acc[nt][2] * sc1 + b0, acc[nt][3] * sc1 + b1);
            *reinterpret_cast<float2*>(out + (size_t)(rbase + 8) * NCLS + col) = v;
        }
    }
}

// ---------------- launch ------------------------------------------------------
extern "C" void kernel_launch(void* const* d_in, const int* in_sizes, int n_in,
                              void* d_out, int out_size) {
    const float* x   = (const float*)d_in[0];
    const int*   src = (const int*)d_in[1];
    const int*   dst = (const int*)d_in[2];
    const float* w1s = (const float*)d_in[3];
    const float* b1s = (const float*)d_in[4];
    const float* w1n = (const float*)d_in[5];
    const float* b1n = (const float*)d_in[6];
    const float* w2s = (const float*)d_in[7];
    const float* b2s = (const float*)d_in[8];
    const float* w2n = (const float*)d_in[9];
    const float* b2n = (const float*)d_in[10];
    const float* wfc = (const float*)d_in[11];
    const float* bfc = (const float*)d_in[12];

    int N_ = in_sizes[0] / 128;
    int E_ = in_sizes[1];

    __half *t1, *t2, *xh, *h1, *h2, *wt1, *wt2, *wtfc;
    float *inv1, *inv2;
    int* degp;
    cudaGetSymbolAddress((void**)&t1, g_t1);
    cudaGetSymbolAddress((void**)&t2, g_t2);
    cudaGetSymbolAddress((void**)&xh, g_xh);
    cudaGetSymbolAddress((void**)&h1, g_h1);
    cudaGetSymbolAddress((void**)&h2, g_h2);
    cudaGetSymbolAddress((void**)&wt1, g_wt1);
    cudaGetSymbolAddress((void**)&wt2, g_wt2);
    cudaGetSymbolAddress((void**)&wtfc, g_wtfc);
    cudaGetSymbolAddress((void**)&inv1, g_inv1);
    cudaGetSymbolAddress((void**)&inv2, g_inv2);
    cudaGetSymbolAddress((void**)&degp, g_deg);

    // host-side stream/event objects: created once on the first (uncaptured) call
    static cudaStream_t s1 = nullptr;
    static cudaEvent_t evFork = nullptr, evJoin = nullptr, evG2 = nullptr;
    static cudaEvent_t evA0 = nullptr, evA1 = nullptr;
    if (s1 == nullptr) {
        cudaStreamCreateWithFlags(&s1, cudaStreamNonBlocking);
        cudaEventCreateWithFlags(&evFork, cudaEventDisableTiming);
        cudaEventCreateWithFlags(&evJoin, cudaEventDisableTiming);
        cudaEventCreateWithFlags(&evG2, cudaEventDisableTiming);
        cudaEventCreateWithFlags(&evA0, cudaEventDisableTiming);
        cudaEventCreateWithFlags(&evA1, cudaEventDisableTiming);
    }

    int eblocks = (E_ + 255) / 256;
    int wblocks = (N_ * 32 + 255) / 256;   // warp-per-node agg
    int gblocks = (N_ + 127) / 128;        // gemm row tiles
    int nb = (N_ + 1023) / 1024;           // scan chunks

    // row halves for the agg2/fc pipelined pair (multiples of 128)
    int nh0 = (((N_ + 1) / 2) + 127) & ~127;
    if (nh0 > N_) nh0 = N_;
    int nh1 = N_ - nh0;

    // ---- fork: CSR build on side stream (overlaps conversions + GEMM1) ----
    cudaEventRecord(evFork, 0);
    cudaStreamWaitEvent(s1, evFork, 0);
    cudaMemsetAsync(degp, 0, (size_t)N_ * sizeof(int), s1);
    count_kernel<<<eblocks, 256, 0, s1>>>(dst, E_);
    scan_block_sum<<<nb, 256, 0, s1>>>(N_);
    scan_block_offsets<<<1, 128, 0, s1>>>(nb, N_);
    scan_write<<<nb, 256, 0, s1>>>(N_);
    scatter_kernel<<<eblocks, 256, 0, s1>>>(src, dst, E_);
    cudaEventRecord(evJoin, s1);

    // ---- main: conversions + layer-1 GEMM ----
    x_to_half<<<(N_ * 32 + 255) / 256, 256>>>(x, xh, N_ * 32);
    w_all_to_half<<<(110592 + 255) / 256, 256>>>(w1s, w1n, w2s, w2n, wfc, wt1, wt2, wtfc);
    gemm_dual_h<<<gblocks, 512>>>(xh, 128, nullptr, wt1, b1s, h1, HD, t1, 128, N_, 128);

    // ---- join: aggregation needs the CSR ----
    cudaStreamWaitEvent(0, evJoin, 0);
    agg_bias_relu_norm<<<wblocks, 256>>>(t1, b1n, h1, inv1, 0, N_);

    // ---- layer 2 ----
    gemm_dual_h<<<gblocks, 512>>>(h1, HD, inv1, wt2, b2s, h2, HD, t2, 128, N_, 256);
    cudaEventRecord(evG2, 0);

    // ---- agg2 / fc pipelined in two row-halves:
    //      s1:   agg2(half0) -> agg2(half1)      (t2 fully written by gemm2)
    //      main: fc(half0) after agg2(half0), overlapping agg2(half1); then fc(half1)
    cudaStreamWaitEvent(s1, evG2, 0);
    {
        int wb0 = (nh0 * 32 + 255) / 256;
        agg_bias_relu_norm<<<wb0, 256, 0, s1>>>(t2, b2n, h2, inv2, 0, nh0);
        cudaEventRecord(evA0, s1);
        if (nh1 > 0) {
            int wb1 = (nh1 * 32 + 255) / 256;
            agg_bias_relu_norm<<<wb1, 256, 0, s1>>>(t2, b2n, h2, inv2, nh0, nh1);
        }
        cudaEventRecord(evA1, s1);
    }
    cudaStreamWaitEvent(0, evA0, 0);
    fc_tc<<<(nh0 + 127) / 128, 256>>>(h2, inv2, wtfc, bfc, (float*)d_out, 0, N_);
    cudaStreamWaitEvent(0, evA1, 0);
    if (nh1 > 0)
        fc_tc<<<(nh1 + 127) / 128, 256>>>(h2, inv2, wtfc, bfc, (float*)d_out, nh0, N_);
}

// round 15
// speedup vs baseline: 1.5850x; 1.0696x over previous
#include <cuda_runtime.h>
#include <cuda_fp16.h>
#include <cstdint>

#define NMAX 100000
#define EMAX 1600000
#define HD   256      // concat hidden dim (2*128)
#define NCLS 40
#define PAD  24       // smem row stride in halves (48B, conflict-free, 16B-aligned)
#define STAGES 3
#define FCPAD 264     // fc W smem row stride in halves
#define SSTG 136      // epilogue staging stride in halves (128 + 8)

// ---------------- scratch (static device globals; no allocation) -------------
__device__ __align__(16) int g_deg[NMAX];
__device__ int   g_rowptr[NMAX + 1];
__device__ int   g_cursor[NMAX];
__device__ int   g_esrc[EMAX];
__device__ int   g_bsum[128];
__device__ int   g_boff[128];
__device__ __align__(16) __half g_t1[(size_t)NMAX * 128];  // layer-1 pre-agg
__device__ __align__(16) __half g_t2[(size_t)NMAX * 128];  // layer-2 pre-agg
__device__ __align__(16) __half g_xh[(size_t)NMAX * 128];  // x in fp16
__device__ __align__(16) __half g_h1[(size_t)NMAX * HD];   // fp16 [self|neigh]
__device__ __align__(16) __half g_h2[(size_t)NMAX * HD];
__device__ __align__(16) __half g_wt1[256 * 128];          // layer1 W^T fp16 [n][k]
__device__ __align__(16) __half g_wt2[256 * 256];          // layer2 W^T fp16 [n][k]
__device__ __align__(16) __half g_wtfc[48 * 256];          // fc W^T fp16, zero-padded
__device__ float g_inv1[NMAX];
__device__ float g_inv2[NMAX];

// ---------------- mma / cp.async helpers --------------------------------------
__device__ __forceinline__ void mma_f16(float& c0, float& c1, float& c2, float& c3,
                                        uint32_t a0, uint32_t a1, uint32_t a2, uint32_t a3,
                                        uint32_t b0, uint32_t b1) {
    asm volatile(
        "mma.sync.aligned.m16n8k16.row.col.f32.f16.f16.f32 "
        "{%0,%1,%2,%3}, {%4,%5,%6,%7}, {%8,%9}, {%0,%1,%2,%3};"
        : "+f"(c0), "+f"(c1), "+f"(c2), "+f"(c3)
        : "r"(a0), "r"(a1), "r"(a2), "r"(a3), "r"(b0), "r"(b1));
}

__device__ __forceinline__ void ldsm_x4(uint32_t* r, uint32_t addr) {
    asm volatile("ldmatrix.sync.aligned.m8n8.x4.shared.b16 {%0,%1,%2,%3}, [%4];"
                 : "=r"(r[0]), "=r"(r[1]), "=r"(r[2]), "=r"(r[3]) : "r"(addr));
}

__device__ __forceinline__ void cp_async16(uint32_t dst, const void* src, bool pred) {
    int sz = pred ? 16 : 0;
    asm volatile("cp.async.cg.shared.global [%0], [%1], 16, %2;"
                 :: "r"(dst), "l"(src), "r"(sz));
}
__device__ __forceinline__ void cp_commit() {
    asm volatile("cp.async.commit_group;" ::: "memory");
}
template <int N>
__device__ __forceinline__ void cp_wait() {
    asm volatile("cp.async.wait_group %0;" :: "n"(N) : "memory");
}

// ---------------- CSR build --------------------------------------------------
__global__ void count_kernel(const int* __restrict__ dst, int e) {
    int i = blockIdx.x * blockDim.x + threadIdx.x;
    if (i < e) atomicAdd(&g_deg[dst[i]], 1);
}

__global__ void scan_block_sum(int n) {
    int b = blockIdx.x, t = threadIdx.x, lane = t & 31, w = t >> 5;
    int base = b * 1024 + t * 4;
    int s = 0;
    if (base + 3 < n) {
        int4 v = *reinterpret_cast<const int4*>(g_deg + base);
        s = v.x + v.y + v.z + v.w;
    } else {
#pragma unroll
        for (int j = 0; j < 4; j++) { int i = base + j; if (i < n) s += g_deg[i]; }
    }
#pragma unroll
    for (int off = 16; off; off >>= 1) s += __shfl_xor_sync(0xffffffffu, s, off);
    __shared__ int ws[8];
    if (lane == 0) ws[w] = s;
    __syncthreads();
    if (t == 0) {
        int tot = 0;
#pragma unroll
        for (int j = 0; j < 8; j++) tot += ws[j];
        g_bsum[b] = tot;
    }
}

__global__ void scan_block_offsets(int nb, int n) {
    int t = threadIdx.x, lane = t & 31, w = t >> 5;
    int v = (t < nb) ? g_bsum[t] : 0;
    int val = v;
#pragma unroll
    for (int off = 1; off < 32; off <<= 1) {
        int u = __shfl_up_sync(0xffffffffu, val, off);
        if (lane >= off) val += u;
    }
    __shared__ int ws[4];
    if (lane == 31) ws[w] = val;
    __syncthreads();
    int add = 0;
#pragma unroll
    for (int j = 0; j < 4; j++) if (j < w) add += ws[j];
    int incl = val + add;
    if (t < nb) g_boff[t] = incl - v;
    if (t == nb - 1) g_rowptr[n] = incl;
}

__global__ void scan_write(int n) {
    int b = blockIdx.x, t = threadIdx.x, lane = t & 31, w = t >> 5;
    int base = b * 1024 + t * 4;
    int4 v = make_int4(0, 0, 0, 0);
    if (base + 3 < n) v = *reinterpret_cast<const int4*>(g_deg + base);
    else {
        v.x = (base < n)     ? g_deg[base]     : 0;
        v.y = (base + 1 < n) ? g_deg[base + 1] : 0;
        v.z = (base + 2 < n) ? g_deg[base + 2] : 0;
        v.w = (base + 3 < n) ? g_deg[base + 3] : 0;
    }
    int s = v.x + v.y + v.z + v.w;
    int val = s;
#pragma unroll
    for (int off = 1; off < 32; off <<= 1) {
        int u = __shfl_up_sync(0xffffffffu, val, off);
        if (lane >= off) val += u;
    }
    __shared__ int ws[8];
    if (lane == 31) ws[w] = val;
    __syncthreads();
    int wadd = 0;
#pragma unroll
    for (int j = 0; j < 8; j++) if (j < w) wadd += ws[j];
    int e0 = g_boff[b] + wadd + (val - s);
    int e1 = e0 + v.x, e2 = e1 + v.y, e3 = e2 + v.z;
    if (base < n)     { g_rowptr[base]     = e0; g_cursor[base]     = e0; }
    if (base + 1 < n) { g_rowptr[base + 1] = e1; g_cursor[base + 1] = e1; }
    if (base + 2 < n) { g_rowptr[base + 2] = e2; g_cursor[base + 2] = e2; }
    if (base + 3 < n) { g_rowptr[base + 3] = e3; g_cursor[base + 3] = e3; }
}

__global__ void scatter_kernel(const int* __restrict__ src,
                               const int* __restrict__ dst, int e) {
    int i = blockIdx.x * blockDim.x + threadIdx.x;
    if (i < e) {
        int d = dst[i];
        int pos = atomicAdd(&g_cursor[d], 1);
        g_esrc[pos] = src[i];
    }
}

// ---------------- fp16 conversions -------------------------------------------
__global__ void x_to_half(const float* __restrict__ x, __half* __restrict__ xh, int n4) {
    int i = blockIdx.x * blockDim.x + threadIdx.x;
    if (i < n4) {
        float4 v = reinterpret_cast<const float4*>(x)[i];
        __half2 p0 = __floats2half2_rn(v.x, v.y);
        __half2 p1 = __floats2half2_rn(v.z, v.w);
        uint2 u;
        u.x = *reinterpret_cast<uint32_t*>(&p0);
        u.y = *reinterpret_cast<uint32_t*>(&p1);
        reinterpret_cast<uint2*>(xh)[i] = u;
    }
}

// all weight conversions in one launch
__global__ void w_all_to_half(const float* __restrict__ w1s, const float* __restrict__ w1n,
                              const float* __restrict__ w2s, const float* __restrict__ w2n,
                              const float* __restrict__ wfc,
                              __half* __restrict__ wt1, __half* __restrict__ wt2,
                              __half* __restrict__ wtfc) {
    int idx = blockIdx.x * blockDim.x + threadIdx.x;
    if (idx < 32768) {
        int n = idx >> 7, k = idx & 127;
        float v = (n < 128) ? w1s[(size_t)k * 128 + n] : w1n[(size_t)k * 128 + (n - 128)];
        wt1[idx] = __float2half_rn(v);
    } else if (idx < 98304) {
        int j = idx - 32768;
        int n = j >> 8, k = j & 255;
        float v = (n < 128) ? w2s[(size_t)k * 128 + n] : w2n[(size_t)k * 128 + (n - 128)];
        wt2[j] = __float2half_rn(v);
    } else if (idx < 110592) {
        int j = idx - 98304;
        int n = j >> 8, k = j & 255;
        float v = (n < NCLS) ? wfc[(size_t)k * NCLS + n] : 0.f;
        wtfc[j] = __float2half_rn(v);
    }
}

// ------ mean aggregation: warp-per-node, uint4/lane, 8 edges/iter (R10 form) --
__device__ __forceinline__ void add8(float* a, uint4 u) {
    float2 f;
    f = __half22float2(*reinterpret_cast<__half2*>(&u.x)); a[0] += f.x; a[1] += f.y;
    f = __half22float2(*reinterpret_cast<__half2*>(&u.y)); a[2] += f.x; a[3] += f.y;
    f = __half22float2(*reinterpret_cast<__half2*>(&u.z)); a[4] += f.x; a[5] += f.y;
    f = __half22float2(*reinterpret_cast<__half2*>(&u.w)); a[6] += f.x; a[7] += f.y;
}

__global__ void agg_bias_relu_norm(const __half* __restrict__ t, const float* __restrict__ bias,
                                   __half* __restrict__ h, float* __restrict__ invn, int n) {
    int gw = (blockIdx.x * blockDim.x + threadIdx.x) >> 5;
    if (gw >= n) return;
    int lane = threadIdx.x & 31;
    int hf = lane >> 4, sub = lane & 15;
    int beg = g_rowptr[gw], end = g_rowptr[gw + 1];
    const uint4* tb = reinterpret_cast<const uint4*>(t);   // 16 uint4 per 128-ch row
    float acc[8] = {0.f, 0.f, 0.f, 0.f, 0.f, 0.f, 0.f, 0.f};
    int e = beg;
    for (; e + 8 <= end; e += 8) {
        int s0 = g_esrc[e + hf];
        int s1 = g_esrc[e + 2 + hf];
        int s2 = g_esrc[e + 4 + hf];
        int s3 = g_esrc[e + 6 + hf];
        uint4 u0 = tb[(size_t)s0 * 16 + sub];
        uint4 u1 = tb[(size_t)s1 * 16 + sub];
        uint4 u2 = tb[(size_t)s2 * 16 + sub];
        uint4 u3 = tb[(size_t)s3 * 16 + sub];
        add8(acc, u0); add8(acc, u1); add8(acc, u2); add8(acc, u3);
    }
    for (; e + 2 <= end; e += 2) {
        int s0 = g_esrc[e + hf];
        uint4 u0 = tb[(size_t)s0 * 16 + sub];
        add8(acc, u0);
    }
    if (e < end && hf == 0) {
        uint4 u0 = tb[(size_t)g_esrc[e] * 16 + sub];
        add8(acc, u0);
    }
#pragma unroll
    for (int j = 0; j < 8; j++) acc[j] += __shfl_xor_sync(0xffffffffu, acc[j], 16);

    int cnt = end - beg;
    float inv = 1.0f / (float)(cnt > 0 ? cnt : 1);
    float ss = 0.f;
    if (hf == 0) {
        float4 b0 = reinterpret_cast<const float4*>(bias)[sub * 2];
        float4 b1 = reinterpret_cast<const float4*>(bias)[sub * 2 + 1];
        float bb[8] = {b0.x, b0.y, b0.z, b0.w, b1.x, b1.y, b1.z, b1.w};
        float o[8];
#pragma unroll
        for (int j = 0; j < 8; j++) {
            o[j] = fmaxf(acc[j] * inv + bb[j], 0.f);
            ss += o[j] * o[j];
        }
        __half* row = h + (size_t)gw * HD;
        __half2 p0 = __floats2half2_rn(o[0], o[1]);
        __half2 p1 = __floats2half2_rn(o[2], o[3]);
        __half2 p2 = __floats2half2_rn(o[4], o[5]);
        __half2 p3 = __floats2half2_rn(o[6], o[7]);
        uint4 wv;
        wv.x = *reinterpret_cast<uint32_t*>(&p0);
        wv.y = *reinterpret_cast<uint32_t*>(&p1);
        wv.z = *reinterpret_cast<uint32_t*>(&p2);
        wv.w = *reinterpret_cast<uint32_t*>(&p3);
        reinterpret_cast<uint4*>(row + 128)[sub] = wv;      // neigh half
        uint4 sv = reinterpret_cast<const uint4*>(row)[sub]; // self half (from GEMM)
        float2 f;
        f = __half22float2(*reinterpret_cast<__half2*>(&sv.x)); ss += f.x * f.x + f.y * f.y;
        f = __half22float2(*reinterpret_cast<__half2*>(&sv.y)); ss += f.x * f.x + f.y * f.y;
        f = __half22float2(*reinterpret_cast<__half2*>(&sv.z)); ss += f.x * f.x + f.y * f.y;
        f = __half22float2(*reinterpret_cast<__half2*>(&sv.w)); ss += f.x * f.x + f.y * f.y;
    }
#pragma unroll
    for (int off = 16; off; off >>= 1) ss += __shfl_xor_sync(0xffffffffu, ss, off);
    if (lane == 0) invn[gw] = 1.0f / fmaxf(sqrtf(ss), 1e-12f);
}

// ---- fused dual-output fp16 GEMM (3-stage cp.async + ldmatrix + m16n8k16) ----
// Epilogue stages each 128x128 output half through smem (reusing Bs) so gmem
// stores are coalesced 16B chunks instead of scattered 4B half2 stores.
__global__ void __launch_bounds__(512)
gemm_dual_h(const __half* __restrict__ A, int lda, const float* __restrict__ rowScale,
            const __half* __restrict__ Wt, const float* __restrict__ bias1,
            __half* __restrict__ out1, int ldo1, __half* __restrict__ out2, int ldo2,
            int M, int K) {
    __shared__ __align__(16) __half As[STAGES][128][PAD];
    __shared__ __align__(16) __half Bs[STAGES][256][PAD];

    const int t = threadIdx.x;
    const int warp = t >> 5, lane = t & 31;
    const int wm = warp & 3, wn = warp >> 2;   // 4 x 4 warp grid
    const int grp = lane >> 2, qid = lane & 3;
    const int row0 = blockIdx.x * 128;

    const uint32_t asb = (uint32_t)__cvta_generic_to_shared(&As[0][0][0]);
    const uint32_t bsb = (uint32_t)__cvta_generic_to_shared(&Bs[0][0][0]);

    float acc[2][8][4];
#pragma unroll
    for (int i = 0; i < 2; i++)
#pragma unroll
        for (int j = 0; j < 8; j++)
#pragma unroll
            for (int c = 0; c < 4; c++) acc[i][j][c] = 0.f;

    auto issue = [&](int tile, int st) {
        int k0 = tile * 16;
        if (t < 256) {
            int row = t >> 1, hf = t & 1;
            int gr = row0 + row;
            cp_async16(asb + (uint32_t)(((st * 128 + row) * PAD + hf * 8) * 2),
                       A + (size_t)gr * lda + k0 + hf * 8, gr < M);
        }
        {
            int nrow = t >> 1, hf = t & 1;
            cp_async16(bsb + (uint32_t)(((st * 256 + nrow) * PAD + hf * 8) * 2),
                       Wt + (size_t)nrow * K + k0 + hf * 8, true);
        }
        cp_commit();
    };

    const int nT = K / 16;
    issue(0, 0);
    issue(1, 1);
    cp_wait<1>();
    __syncthreads();

    for (int tile = 0; tile < nT; ++tile) {
        int cur = tile % STAGES;
        uint32_t af[2][4], bq[4][4];
#pragma unroll
        for (int mt = 0; mt < 2; ++mt) {
            int m0 = wm * 32 + mt * 16;
            int arow = m0 + (lane & 15);
            int acol = (lane >> 4) * 8;
            ldsm_x4(af[mt], asb + (uint32_t)(((cur * 128 + arow) * PAD + acol) * 2));
        }
#pragma unroll
        for (int np = 0; np < 4; ++np) {
            int n0 = wn * 64 + np * 16;
            int brow = n0 + ((lane >> 4) << 3) + (lane & 7);
            int bcol = ((lane >> 3) & 1) * 8;
            ldsm_x4(bq[np], bsb + (uint32_t)(((cur * 256 + brow) * PAD + bcol) * 2));
        }
#pragma unroll
        for (int mt = 0; mt < 2; ++mt)
#pragma unroll
            for (int nt = 0; nt < 8; ++nt)
                mma_f16(acc[mt][nt][0], acc[mt][nt][1], acc[mt][nt][2], acc[mt][nt][3],
                        af[mt][0], af[mt][1], af[mt][2], af[mt][3],
                        bq[nt >> 1][(nt & 1) * 2], bq[nt >> 1][(nt & 1) * 2 + 1]);

        if (tile + 2 < nT) {
            issue(tile + 2, (tile + 2) % STAGES);
            cp_wait<1>();
        } else {
            cp_wait<0>();
        }
        __syncthreads();
    }

    // ---- epilogue: stage each 128-col half in smem, then coalesced 16B stores.
    // Bs (36.8KB) is dead now; reuse as 128 x SSTG half staging tile (34.8KB).
    __half* stg = &Bs[0][0][0];
    float sc[2][2];   // [mt][0]=row, [mt][1]=row+8
#pragma unroll
    for (int mt = 0; mt < 2; ++mt) {
        int rbase = row0 + wm * 32 + mt * 16 + grp;
        sc[mt][0] = 1.f; sc[mt][1] = 1.f;
        if (rowScale != nullptr) {
            if (rbase < M)     sc[mt][0] = rowScale[rbase];
            if (rbase + 8 < M) sc[mt][1] = rowScale[rbase + 8];
        }
    }

#pragma unroll
    for (int ph = 0; ph < 2; ++ph) {      // ph0: cols 0-127 -> out1 ; ph1: -> out2
        __syncthreads();
        if ((wn >> 1) == ph) {            // wn {0,1} handle ph0; {2,3} handle ph1
#pragma unroll
            for (int mt = 0; mt < 2; ++mt) {
                int lrow = wm * 32 + mt * 16 + grp;
#pragma unroll
                for (int nt = 0; nt < 8; ++nt) {
                    int lcol = (wn & 1) * 64 + nt * 8 + qid * 2;
                    __half2 v0, v1;
                    if (ph == 0) {
                        float b0 = bias1[lcol], b1 = bias1[lcol + 1];
                        v0 = __floats2half2_rn(fmaxf(acc[mt][nt][0] * sc[mt][0] + b0, 0.f),
                                               fmaxf(acc[mt][nt][1] * sc[mt][0] + b1, 0.f));
                        v1 = __floats2half2_rn(fmaxf(acc[mt][nt][2] * sc[mt][1] + b0, 0.f),
                                               fmaxf(acc[mt][nt][3] * sc[mt][1] + b1, 0.f));
                    } else {
                        v0 = __floats2half2_rn(acc[mt][nt][0] * sc[mt][0],
                                               acc[mt][nt][1] * sc[mt][0]);
                        v1 = __floats2half2_rn(acc[mt][nt][2] * sc[mt][1],
                                               acc[mt][nt][3] * sc[mt][1]);
                    }
                    *reinterpret_cast<__half2*>(&stg[lrow * SSTG + lcol]) = v0;
                    *reinterpret_cast<__half2*>(&stg[(lrow + 8) * SSTG + lcol]) = v1;
                }
            }
        }
        __syncthreads();
        __half* dst = (ph == 0) ? out1 : out2;
        int ld = (ph == 0) ? ldo1 : ldo2;
        for (int i = t; i < 2048; i += 512) {   // 128 rows x 16 uint4
            int r = i >> 4, c8 = i & 15;
            int gr2 = row0 + r;
            if (gr2 < M)
                *reinterpret_cast<uint4*>(dst + (size_t)gr2 * ld + c8 * 8) =
                    *reinterpret_cast<const uint4*>(&stg[r * SSTG + c8 * 8]);
        }
    }
}

// ---- tensor-core FC head: out[M x 40] fp32 = (A .* inv) @ Wfc + bias ---------
__global__ void __launch_bounds__(256)
fc_tc(const __half* __restrict__ A, const float* __restrict__ inv,
      const __half* __restrict__ Wt, const float* __restrict__ bias,
      float* __restrict__ out, int M) {
    __shared__ __align__(16) __half As[STAGES][128][PAD];
    __shared__ __align__(16) __half Bs[48][FCPAD];

    const int t = threadIdx.x;
    const int warp = t >> 5, lane = t & 31;
    const int grp = lane >> 2, qid = lane & 3;
    const int row0 = blockIdx.x * 128;

    const uint32_t asb = (uint32_t)__cvta_generic_to_shared(&As[0][0][0]);
    const uint32_t bsb = (uint32_t)__cvta_generic_to_shared(&Bs[0][0]);

    for (int i = t; i < 1536; i += 256) {
        int r = i >> 5, c = (i & 31) << 3;
        *reinterpret_cast<uint4*>(&Bs[r][c]) =
            *reinterpret_cast<const uint4*>(Wt + (size_t)r * 256 + c);
    }

    float acc[5][4];
#pragma unroll
    for (int j = 0; j < 5; j++)
#pragma unroll
        for (int c = 0; c < 4; c++) acc[j][c] = 0.f;

    auto issueA = [&](int tile, int st) {
        int row = t >> 1, hf = t & 1;
        int gr = row0 + row;
        cp_async16(asb + (uint32_t)(((st * 128 + row) * PAD + hf * 8) * 2),
                   A + (size_t)gr * HD + tile * 16 + hf * 8, gr < M);
        cp_commit();
    };

    issueA(0, 0);
    issueA(1, 1);
    cp_wait<1>();
    __syncthreads();

    const int nT = HD / 16;  // 16
    for (int tile = 0; tile < nT; ++tile) {
        int cur = tile % STAGES;
        uint32_t af[4], bq[3][4];
        {
            int arow = warp * 16 + (lane & 15);
            int acol = (lane >> 4) * 8;
            ldsm_x4(af, asb + (uint32_t)(((cur * 128 + arow) * PAD + acol) * 2));
        }
#pragma unroll
        for (int np = 0; np < 3; ++np) {
            int brow = np * 16 + ((lane >> 4) << 3) + (lane & 7);
            int bcol = tile * 16 + ((lane >> 3) & 1) * 8;
            ldsm_x4(bq[np], bsb + (uint32_t)((brow * FCPAD + bcol) * 2));
        }
#pragma unroll
        for (int nt = 0; nt < 5; ++nt)
            mma_f16(acc[nt][0], acc[nt][1], acc[nt][2], acc[nt][3],
                    af[0], af[1], af[2], af[3],
                    bq[nt >> 1][(nt & 1) * 2], bq[nt >> 1][(nt & 1) * 2 + 1]);

        if (tile + 2 < nT) {
            issueA(tile + 2, (tile + 2) % STAGES);
            cp_wait<1>();
        } else {
            cp_wait<0>();
        }
        __syncthreads();
    }

    int rbase = row0 + warp * 16 + grp;
    float sc0 = (rbase < M) ? inv[rbase] : 0.f;
    float sc1 = (rbase + 8 < M) ? inv[rbase + 8] : 0.f;
#pragma unroll
    for (int nt = 0; nt < 5; ++nt) {
        int col = nt * 8 + qid * 2;
        float b0 = bias[col], b1 = bias[col + 1];
        if (rbase < M) {
            float2 v = make_float2(acc[nt][0] * sc0 + b0, acc[nt][1] * sc0 + b1);
            *reinterpret_cast<float2*>(out + (size_t)rbase * NCLS + col) = v;
        }
        if (rbase + 8 < M) {
            float2 v = make_float2(acc[nt][2] * sc1 + b0, acc[nt][3] * sc1 + b1);
            *reinterpret_cast<float2*>(out + (size_t)(rbase + 8) * NCLS + col) = v;
        }
    }
}

// ---------------- launch ------------------------------------------------------
extern "C" void kernel_launch(void* const* d_in, const int* in_sizes, int n_in,
                              void* d_out, int out_size) {
    const float* x   = (const float*)d_in[0];
    const int*   src = (const int*)d_in[1];
    const int*   dst = (const int*)d_in[2];
    const float* w1s = (const float*)d_in[3];
    const float* b1s = (const float*)d_in[4];
    const float* w1n = (const float*)d_in[5];
    const float* b1n = (const float*)d_in[6];
    const float* w2s = (const float*)d_in[7];
    const float* b2s = (const float*)d_in[8];
    const float* w2n = (const float*)d_in[9];
    const float* b2n = (const float*)d_in[10];
    const float* wfc = (const float*)d_in[11];
    const float* bfc = (const float*)d_in[12];

    int N_ = in_sizes[0] / 128;
    int E_ = in_sizes[1];

    __half *t1, *t2, *xh, *h1, *h2, *wt1, *wt2, *wtfc;
    float *inv1, *inv2;
    int* degp;
    cudaGetSymbolAddress((void**)&t1, g_t1);
    cudaGetSymbolAddress((void**)&t2, g_t2);
    cudaGetSymbolAddress((void**)&xh, g_xh);
    cudaGetSymbolAddress((void**)&h1, g_h1);
    cudaGetSymbolAddress((void**)&h2, g_h2);
    cudaGetSymbolAddress((void**)&wt1, g_wt1);
    cudaGetSymbolAddress((void**)&wt2, g_wt2);
    cudaGetSymbolAddress((void**)&wtfc, g_wtfc);
    cudaGetSymbolAddress((void**)&inv1, g_inv1);
    cudaGetSymbolAddress((void**)&inv2, g_inv2);
    cudaGetSymbolAddress((void**)&degp, g_deg);

    // host-side stream/event objects: created once on the first (uncaptured) call
    static cudaStream_t s1 = nullptr;
    static cudaEvent_t evFork = nullptr, evJoin = nullptr;
    if (s1 == nullptr) {
        cudaStreamCreateWithFlags(&s1, cudaStreamNonBlocking);
        cudaEventCreateWithFlags(&evFork, cudaEventDisableTiming);
        cudaEventCreateWithFlags(&evJoin, cudaEventDisableTiming);
    }

    int eblocks = (E_ + 255) / 256;
    int wblocks = (N_ * 32 + 255) / 256;   // warp-per-node agg
    int gblocks = (N_ + 127) / 128;        // gemm row tiles
    int nb = (N_ + 1023) / 1024;           // scan chunks

    // ---- fork: CSR build on side stream (overlaps conversions + GEMM1) ----
    cudaEventRecord(evFork, 0);
    cudaStreamWaitEvent(s1, evFork, 0);
    cudaMemsetAsync(degp, 0, (size_t)N_ * sizeof(int), s1);
    count_kernel<<<eblocks, 256, 0, s1>>>(dst, E_);
    scan_block_sum<<<nb, 256, 0, s1>>>(N_);
    scan_block_offsets<<<1, 128, 0, s1>>>(nb, N_);
    scan_write<<<nb, 256, 0, s1>>>(N_);
    scatter_kernel<<<eblocks, 256, 0, s1>>>(src, dst, E_);
    cudaEventRecord(evJoin, s1);

    // ---- main: conversions + layer-1 GEMM ----
    x_to_half<<<(N_ * 32 + 255) / 256, 256>>>(x, xh, N_ * 32);
    w_all_to_half<<<(110592 + 255) / 256, 256>>>(w1s, w1n, w2s, w2n, wfc, wt1, wt2, wtfc);
    gemm_dual_h<<<gblocks, 512>>>(xh, 128, nullptr, wt1, b1s, h1, HD, t1, 128, N_, 128);

    // ---- join: aggregation needs the CSR ----
    cudaStreamWaitEvent(0, evJoin, 0);
    agg_bias_relu_norm<<<wblocks, 256>>>(t1, b1n, h1, inv1, N_);

    // ---- layer 2 ----
    gemm_dual_h<<<gblocks, 512>>>(h1, HD, inv1, wt2, b2s, h2, HD, t2, 128, N_, 256);
    agg_bias_relu_norm<<<wblocks, 256>>>(t2, b2n, h2, inv2, N_);

    // ---- head (tensor-core) ----
    fc_tc<<<gblocks, 256>>>(h2, inv2, wtfc, bfc, (float*)d_out, N_);
}